// round 1
// baseline (speedup 1.0000x reference)
#include <cuda_runtime.h>
#include <math.h>

// Problem constants
#define NB 4
#define NT 4096
#define NC 1024
#define ND 64

#define STRIDE 65  // odd stride -> conflict-light smem

// Scratch for q, k, v projections (static device globals: allocation-free)
__device__ float g_q[NB * NT * ND];
__device__ float g_k[NB * NT * ND];
__device__ float g_v[NB * NT * ND];

// ---------------------------------------------------------------------------
// Kernel 1: QKV projection.  out[r][c] = sum_k x[r][k] * W[c][k] + b[c]
// M = NB*NT = 16384 rows, K = 1024, N = 64.  Tile 64x64, K-chunk 32.
// grid = (256, 3), block = 256 (16x16 threads, 4x4 micro-tile per thread)
// ---------------------------------------------------------------------------
__global__ __launch_bounds__(256) void qkv_kernel(
    const float* __restrict__ x,
    const float* __restrict__ Wq, const float* __restrict__ bq,
    const float* __restrict__ Wk, const float* __restrict__ bk,
    const float* __restrict__ Wv, const float* __restrict__ bv)
{
    const float* W;
    const float* bias;
    float* out;
    int sel = blockIdx.y;
    if (sel == 0)      { W = Wq; bias = bq; out = g_q; }
    else if (sel == 1) { W = Wk; bias = bk; out = g_k; }
    else               { W = Wv; bias = bv; out = g_v; }

    __shared__ float Xs[64 * 33];
    __shared__ float Ws[64 * 33];

    int tid = threadIdx.x;
    int tx = tid & 15;
    int ty = tid >> 4;
    int row0 = blockIdx.x * 64;

    float acc[4][4] = {};

    for (int k0 = 0; k0 < NC; k0 += 32) {
        // Load X tile (64 rows x 32 k) and W tile (64 cols x 32 k), coalesced.
#pragma unroll
        for (int i = 0; i < 8; i++) {
            int idx = tid + i * 256;      // 0..2047
            int r = idx >> 5;
            int kk = idx & 31;
            Xs[r * 33 + kk] = x[(size_t)(row0 + r) * NC + k0 + kk];
            Ws[r * 33 + kk] = W[(size_t)r * NC + k0 + kk];
        }
        __syncthreads();

#pragma unroll 8
        for (int kk = 0; kk < 32; kk++) {
            float a[4], bvals[4];
#pragma unroll
            for (int i = 0; i < 4; i++) a[i] = Xs[(ty * 4 + i) * 33 + kk];
#pragma unroll
            for (int j = 0; j < 4; j++) bvals[j] = Ws[(tx * 4 + j) * 33 + kk];
#pragma unroll
            for (int i = 0; i < 4; i++)
#pragma unroll
                for (int j = 0; j < 4; j++)
                    acc[i][j] = fmaf(a[i], bvals[j], acc[i][j]);
        }
        __syncthreads();
    }

#pragma unroll
    for (int j = 0; j < 4; j++) {
        float bb = bias[tx * 4 + j];
#pragma unroll
        for (int i = 0; i < 4; i++) acc[i][j] += bb;
    }

#pragma unroll
    for (int i = 0; i < 4; i++) {
        float4 val = make_float4(acc[i][0], acc[i][1], acc[i][2], acc[i][3]);
        *(float4*)&out[(size_t)(row0 + ty * 4 + i) * ND + tx * 4] = val;
    }
}

// ---------------------------------------------------------------------------
// Kernel 2: flash attention, fp32.
// grid = (NT/64, NB), block = 256 (16x16, 4x4 micro-tile).
// Per block: q rows [q0, q0+64).  Loop over 64 key tiles of 64 tokens.
// Online softmax with per-row (m, l) kept redundantly across the 16 tx lanes.
// ---------------------------------------------------------------------------
__global__ __launch_bounds__(256) void attn_kernel(float* __restrict__ out)
{
    extern __shared__ float sm[];
    float* Qs  = sm;                    // 64 x STRIDE  (row r, col d), pre-scaled by 8
    float* KVs = sm + 64 * STRIDE;      // 64 x STRIDE  (K tile, then V tile)
    float* Ps  = sm + 2 * 64 * STRIDE;  // 64 x STRIDE  (softmax probs)

    int tid = threadIdx.x;
    int tx = tid & 15;
    int ty = tid >> 4;
    int b  = blockIdx.y;
    int q0 = blockIdx.x * 64;

    const float* q = g_q + (size_t)b * NT * ND;
    const float* k = g_k + (size_t)b * NT * ND;
    const float* v = g_v + (size_t)b * NT * ND;

    // Load Q tile once, folding in the score scale (ref divides by D^-0.5 => *8)
#pragma unroll
    for (int i = 0; i < 16; i++) {
        int idx = tid + i * 256;        // 0..4095
        int r = idx >> 6;
        int d = idx & 63;
        Qs[r * STRIDE + d] = q[(size_t)(q0 + r) * ND + d] * 8.0f;
    }
    __syncthreads();

    float o[4][4] = {};
    float m[4], l[4];
#pragma unroll
    for (int i = 0; i < 4; i++) { m[i] = -1e30f; l[i] = 0.0f; }

    for (int kt = 0; kt < NT / 64; kt++) {
        // ---- load K tile (token-major [c][d]) ----
#pragma unroll
        for (int i = 0; i < 16; i++) {
            int idx = tid + i * 256;
            int r = idx >> 6;
            int d = idx & 63;
            KVs[r * STRIDE + d] = k[(size_t)(kt * 64 + r) * ND + d];
        }
        __syncthreads();

        // ---- S = Q * K^T  (thread owns rows 4ty..+3, cols 4tx..+3) ----
        float s[4][4] = {};
#pragma unroll 8
        for (int d = 0; d < 64; d++) {
            float a[4], bb[4];
#pragma unroll
            for (int i = 0; i < 4; i++) a[i] = Qs[(ty * 4 + i) * STRIDE + d];
#pragma unroll
            for (int j = 0; j < 4; j++) bb[j] = KVs[(tx * 4 + j) * STRIDE + d];
#pragma unroll
            for (int i = 0; i < 4; i++)
#pragma unroll
                for (int j = 0; j < 4; j++)
                    s[i][j] = fmaf(a[i], bb[j], s[i][j]);
        }

        // ---- online softmax update (row reductions across the 16 tx lanes) ----
        float alpha[4];
#pragma unroll
        for (int i = 0; i < 4; i++) {
            float tmax = fmaxf(fmaxf(s[i][0], s[i][1]), fmaxf(s[i][2], s[i][3]));
#pragma unroll
            for (int w = 1; w <= 8; w <<= 1)
                tmax = fmaxf(tmax, __shfl_xor_sync(0xffffffffu, tmax, w));
            float mnew = fmaxf(m[i], tmax);
            alpha[i] = __expf(m[i] - mnew);

            float su = 0.0f;
#pragma unroll
            for (int j = 0; j < 4; j++) {
                s[i][j] = __expf(s[i][j] - mnew);
                su += s[i][j];
            }
#pragma unroll
            for (int w = 1; w <= 8; w <<= 1)
                su += __shfl_xor_sync(0xffffffffu, su, w);

            l[i] = l[i] * alpha[i] + su;
            m[i] = mnew;
        }

        // rescale O accumulators
#pragma unroll
        for (int i = 0; i < 4; i++)
#pragma unroll
            for (int j = 0; j < 4; j++)
                o[i][j] *= alpha[i];

        // write P to smem
#pragma unroll
        for (int i = 0; i < 4; i++)
#pragma unroll
            for (int j = 0; j < 4; j++)
                Ps[(ty * 4 + i) * STRIDE + tx * 4 + j] = s[i][j];
        __syncthreads();   // all K reads done + P visible

        // ---- load V tile into KVs ----
#pragma unroll
        for (int i = 0; i < 16; i++) {
            int idx = tid + i * 256;
            int r = idx >> 6;
            int d = idx & 63;
            KVs[r * STRIDE + d] = v[(size_t)(kt * 64 + r) * ND + d];
        }
        __syncthreads();

        // ---- O += P * V ----
#pragma unroll 8
        for (int ss = 0; ss < 64; ss++) {
            float a[4], bb[4];
#pragma unroll
            for (int i = 0; i < 4; i++) a[i] = Ps[(ty * 4 + i) * STRIDE + ss];
#pragma unroll
            for (int j = 0; j < 4; j++) bb[j] = KVs[ss * STRIDE + tx * 4 + j];
#pragma unroll
            for (int i = 0; i < 4; i++)
#pragma unroll
                for (int j = 0; j < 4; j++)
                    o[i][j] = fmaf(a[i], bb[j], o[i][j]);
        }
        __syncthreads();   // V + P reads done before next tile overwrites
    }

    // ---- normalize and write output ----
#pragma unroll
    for (int i = 0; i < 4; i++) {
        float inv = 1.0f / l[i];
        float4 val = make_float4(o[i][0] * inv, o[i][1] * inv,
                                 o[i][2] * inv, o[i][3] * inv);
        *(float4*)&out[((size_t)b * NT + q0 + ty * 4 + i) * ND + tx * 4] = val;
    }
}

// ---------------------------------------------------------------------------
extern "C" void kernel_launch(void* const* d_in, const int* in_sizes, int n_in,
                              void* d_out, int out_size)
{
    (void)in_sizes; (void)n_in; (void)out_size;
    const float* x  = (const float*)d_in[0];
    const float* Wq = (const float*)d_in[1];
    const float* bq = (const float*)d_in[2];
    const float* Wk = (const float*)d_in[3];
    const float* bk = (const float*)d_in[4];
    const float* Wv = (const float*)d_in[5];
    const float* bv = (const float*)d_in[6];
    float* out = (float*)d_out;

    // QKV projections
    qkv_kernel<<<dim3((NB * NT) / 64, 3), 256>>>(x, Wq, bq, Wk, bk, Wv, bv);

    // Flash attention (49,920 B dynamic smem > 48KB default -> raise cap;
    // cudaFuncSetAttribute executes immediately, capture-safe, no allocation)
    size_t smem = 3 * 64 * STRIDE * sizeof(float);
    cudaFuncSetAttribute(attn_kernel,
                         cudaFuncAttributeMaxDynamicSharedMemorySize,
                         (int)smem);
    attn_kernel<<<dim3(NT / 64, NB), 256, smem>>>(out);
}

// round 3
// speedup vs baseline: 1.1785x; 1.1785x over previous
#include <cuda_runtime.h>
#include <math.h>

// Problem constants
#define NB 4
#define NT 4096
#define NC 1024
#define ND 64

#define SP 68   // padded row stride (floats): 272B rows -> 16B-aligned, conflict-light

// Scratch for q, k, v projections (static device globals: allocation-free)
__device__ float g_q[NB * NT * ND];
__device__ float g_k[NB * NT * ND];
__device__ float g_v[NB * NT * ND];

// ---------------------------------------------------------------------------
// Kernel 1: QKV projection.  out[r][c] = sum_k x[r][k] * W[c][k] + b[c]
// M = NB*NT = 16384 rows, K = 1024, N = 64.  Tile 64x64, K-chunk 32.
// Tiles staged k-major so inner-loop smem reads are LDS.128.
// grid = (256, 3), block = 256 (16x16 threads, 4x4 micro-tile per thread)
// ---------------------------------------------------------------------------
__global__ __launch_bounds__(256) void qkv_kernel(
    const float* __restrict__ x,
    const float* __restrict__ Wq, const float* __restrict__ bq,
    const float* __restrict__ Wk, const float* __restrict__ bk,
    const float* __restrict__ Wv, const float* __restrict__ bv)
{
    const float* W;
    const float* bias;
    float* out;
    int sel = blockIdx.y;
    if (sel == 0)      { W = Wq; bias = bq; out = g_q; }
    else if (sel == 1) { W = Wk; bias = bk; out = g_k; }
    else               { W = Wv; bias = bv; out = g_v; }

    __shared__ float Xs[32 * SP];   // [kk][row]
    __shared__ float Ws[32 * SP];   // [kk][col]

    int tid = threadIdx.x;
    int tx = tid & 15;
    int ty = tid >> 4;
    int row0 = blockIdx.x * 64;

    float acc[4][4] = {};

    for (int k0 = 0; k0 < NC; k0 += 32) {
        // Stage tiles transposed (k-major). Gmem reads stay fully coalesced.
#pragma unroll
        for (int i = 0; i < 8; i++) {
            int idx = tid + i * 256;      // 0..2047
            int r = idx >> 5;
            int kk = idx & 31;
            Xs[kk * SP + r] = x[(size_t)(row0 + r) * NC + k0 + kk];
            Ws[kk * SP + r] = W[(size_t)r * NC + k0 + kk];
        }
        __syncthreads();

#pragma unroll
        for (int kk = 0; kk < 32; kk++) {
            float4 a4 = *(const float4*)&Xs[kk * SP + ty * 4];
            float4 b4 = *(const float4*)&Ws[kk * SP + tx * 4];
            float a[4] = {a4.x, a4.y, a4.z, a4.w};
            float bb[4] = {b4.x, b4.y, b4.z, b4.w};
#pragma unroll
            for (int i = 0; i < 4; i++)
#pragma unroll
                for (int j = 0; j < 4; j++)
                    acc[i][j] = fmaf(a[i], bb[j], acc[i][j]);
        }
        __syncthreads();
    }

#pragma unroll
    for (int j = 0; j < 4; j++) {
        float bb = bias[tx * 4 + j];
#pragma unroll
        for (int i = 0; i < 4; i++) acc[i][j] += bb;
    }

#pragma unroll
    for (int i = 0; i < 4; i++) {
        float4 val = make_float4(acc[i][0], acc[i][1], acc[i][2], acc[i][3]);
        *(float4*)&out[(size_t)(row0 + ty * 4 + i) * ND + tx * 4] = val;
    }
}

// ---------------------------------------------------------------------------
// Kernel 2: flash attention, fp32, vectorized smem access.
// grid = (NT/64, NB), block = 256 (16x16, 4x4 micro-tile).
// Q and K tiles staged d-major ([d][token]) so the S=QK^T inner loop is
// 2x LDS.128 + 16 FFMA per d-step. P stored with STS.128; PV loop grouped
// by 4 kv-tokens so P and V reads are LDS.128 too.
// ---------------------------------------------------------------------------
__global__ __launch_bounds__(256) void attn_kernel(float* __restrict__ out)
{
    extern __shared__ float sm[];
    float* Qs  = sm;                 // [d][r]  64 x SP, pre-scaled by 8
    float* KVs = sm + 64 * SP;       // K: [d][c] 64 x SP;  V: [s][c] 64 x SP
    float* Ps  = sm + 2 * 64 * SP;   // [r][s]  64 x SP

    int tid = threadIdx.x;
    int tx = tid & 15;
    int ty = tid >> 4;
    int b  = blockIdx.y;
    int q0 = blockIdx.x * 64;

    const float* q = g_q + (size_t)b * NT * ND;
    const float* k = g_k + (size_t)b * NT * ND;
    const float* v = g_v + (size_t)b * NT * ND;

    // Load Q tile once, d-major, folding in the score scale (ref: /D^-0.5 => *8)
#pragma unroll
    for (int i = 0; i < 16; i++) {
        int idx = tid + i * 256;        // 0..4095
        int r = idx >> 6;
        int d = idx & 63;
        Qs[d * SP + r] = q[(size_t)(q0 + r) * ND + d] * 8.0f;
    }

    float o[4][4] = {};
    float m[4], l[4];
#pragma unroll
    for (int i = 0; i < 4; i++) { m[i] = -1e30f; l[i] = 0.0f; }

    for (int kt = 0; kt < NT / 64; kt++) {
        __syncthreads();   // prev-iter PV reads of KVs/Ps done; Q visible (iter 0)

        // ---- stage K tile d-major: KVs[d][c] ----
#pragma unroll
        for (int i = 0; i < 16; i++) {
            int idx = tid + i * 256;
            int r = idx >> 6;
            int d = idx & 63;
            KVs[d * SP + r] = k[(size_t)(kt * 64 + r) * ND + d];
        }
        __syncthreads();

        // ---- S = Q * K^T : 2x LDS.128 + 16 FFMA per d ----
        float s[4][4] = {};
#pragma unroll
        for (int d = 0; d < 64; d++) {
            float4 qa4 = *(const float4*)&Qs[d * SP + ty * 4];
            float4 kb4 = *(const float4*)&KVs[d * SP + tx * 4];
            float a[4] = {qa4.x, qa4.y, qa4.z, qa4.w};
            float bb[4] = {kb4.x, kb4.y, kb4.z, kb4.w};
#pragma unroll
            for (int i = 0; i < 4; i++)
#pragma unroll
                for (int j = 0; j < 4; j++)
                    s[i][j] = fmaf(a[i], bb[j], s[i][j]);
        }

        // ---- online softmax update (row reductions across the 16 tx lanes) ----
        float alpha[4];
#pragma unroll
        for (int i = 0; i < 4; i++) {
            float tmax = fmaxf(fmaxf(s[i][0], s[i][1]), fmaxf(s[i][2], s[i][3]));
#pragma unroll
            for (int w = 1; w <= 8; w <<= 1)
                tmax = fmaxf(tmax, __shfl_xor_sync(0xffffffffu, tmax, w));
            float mnew = fmaxf(m[i], tmax);
            alpha[i] = __expf(m[i] - mnew);

            float su = 0.0f;
#pragma unroll
            for (int j = 0; j < 4; j++) {
                s[i][j] = __expf(s[i][j] - mnew);
                su += s[i][j];
            }
#pragma unroll
            for (int w = 1; w <= 8; w <<= 1)
                su += __shfl_xor_sync(0xffffffffu, su, w);

            l[i] = l[i] * alpha[i] + su;
            m[i] = mnew;
        }

        // rescale O accumulators
#pragma unroll
        for (int i = 0; i < 4; i++)
#pragma unroll
            for (int j = 0; j < 4; j++)
                o[i][j] *= alpha[i];

        // write P rows with STS.128
#pragma unroll
        for (int i = 0; i < 4; i++) {
            float4 val = make_float4(s[i][0], s[i][1], s[i][2], s[i][3]);
            *(float4*)&Ps[(ty * 4 + i) * SP + tx * 4] = val;
        }
        __syncthreads();   // P visible; K reads done before V overwrites KVs

        // ---- stage V tile row-major: KVs[s][c] ----
#pragma unroll
        for (int i = 0; i < 16; i++) {
            int idx = tid + i * 256;
            int r = idx >> 6;
            int d = idx & 63;
            KVs[r * SP + d] = v[(size_t)(kt * 64 + r) * ND + d];
        }
        __syncthreads();

        // ---- O += P * V, grouped by 4 kv-tokens: all LDS.128 ----
#pragma unroll 4
        for (int g = 0; g < 16; g++) {
            float a[4][4];
#pragma unroll
            for (int i = 0; i < 4; i++)
                *(float4*)&a[i][0] = *(const float4*)&Ps[(ty * 4 + i) * SP + g * 4];
#pragma unroll
            for (int u = 0; u < 4; u++) {
                float4 vb4 = *(const float4*)&KVs[(g * 4 + u) * SP + tx * 4];
                float bb[4] = {vb4.x, vb4.y, vb4.z, vb4.w};
#pragma unroll
                for (int i = 0; i < 4; i++)
#pragma unroll
                    for (int j = 0; j < 4; j++)
                        o[i][j] = fmaf(a[i][u], bb[j], o[i][j]);
            }
        }
    }

    // ---- normalize and write output ----
#pragma unroll
    for (int i = 0; i < 4; i++) {
        float inv = 1.0f / l[i];
        float4 val = make_float4(o[i][0] * inv, o[i][1] * inv,
                                 o[i][2] * inv, o[i][3] * inv);
        *(float4*)&out[((size_t)b * NT + q0 + ty * 4 + i) * ND + tx * 4] = val;
    }
}

// ---------------------------------------------------------------------------
extern "C" void kernel_launch(void* const* d_in, const int* in_sizes, int n_in,
                              void* d_out, int out_size)
{
    (void)in_sizes; (void)n_in; (void)out_size;
    const float* x  = (const float*)d_in[0];
    const float* Wq = (const float*)d_in[1];
    const float* bq = (const float*)d_in[2];
    const float* Wk = (const float*)d_in[3];
    const float* bk = (const float*)d_in[4];
    const float* Wv = (const float*)d_in[5];
    const float* bv = (const float*)d_in[6];
    float* out = (float*)d_out;

    // QKV projections
    qkv_kernel<<<dim3((NB * NT) / 64, 3), 256>>>(x, Wq, bq, Wk, bk, Wv, bv);

    // Flash attention (52,224 B dynamic smem > 48KB default -> raise cap;
    // cudaFuncSetAttribute executes immediately, capture-safe, no allocation)
    size_t smem = 3 * 64 * SP * sizeof(float);
    cudaFuncSetAttribute(attn_kernel,
                         cudaFuncAttributeMaxDynamicSharedMemorySize,
                         (int)smem);
    attn_kernel<<<dim3(NT / 64, NB), 256, smem>>>(out);
}

// round 5
// speedup vs baseline: 1.8706x; 1.5873x over previous
#include <cuda_runtime.h>
#include <cuda_bf16.h>
#include <math.h>

// Problem constants
#define NB 4
#define NT 4096
#define NC 1024
#define ND 64
#define BQ 128          // q rows per CTA
#define BK 64           // kv tokens per tile

// Scratch for q, k, v projections (static device globals: allocation-free)
__device__ float g_q[NB * NT * ND];
__device__ float g_k[NB * NT * ND];
__device__ float g_v[NB * NT * ND];

// ===========================================================================
// Helpers
// ===========================================================================
__device__ __forceinline__ unsigned smem_to_u32(const void* p) {
    unsigned a;
    asm("{ .reg .u64 t; cvta.to.shared.u64 t, %1; cvt.u32.u64 %0, t; }"
        : "=r"(a) : "l"(p));
    return a;
}

// bf16 hi/lo split of a float pair, packed little-endian (x in low half)
__device__ __forceinline__ void split2(float x, float y, unsigned& hp, unsigned& lp) {
    __nv_bfloat16 hx = __float2bfloat16(x);
    __nv_bfloat16 hy = __float2bfloat16(y);
    float rx = x - __bfloat162float(hx);
    float ry = y - __bfloat162float(hy);
    __nv_bfloat16 lx = __float2bfloat16(rx);
    __nv_bfloat16 ly = __float2bfloat16(ry);
    hp = ((unsigned)__bfloat16_as_ushort(hy) << 16) | __bfloat16_as_ushort(hx);
    lp = ((unsigned)__bfloat16_as_ushort(ly) << 16) | __bfloat16_as_ushort(lx);
}

// ldmatrix x4, non-transposed
__device__ __forceinline__ void ldsm4(unsigned r[4], unsigned addr) {
    asm volatile("ldmatrix.sync.aligned.m8n8.x4.shared.b16 {%0,%1,%2,%3}, [%4];"
        : "=r"(r[0]), "=r"(r[1]), "=r"(r[2]), "=r"(r[3]) : "r"(addr));
}
// ldmatrix x4, transposed (b16)
__device__ __forceinline__ void ldsm4t(unsigned r[4], unsigned addr) {
    asm volatile("ldmatrix.sync.aligned.m8n8.x4.trans.shared.b16 {%0,%1,%2,%3}, [%4];"
        : "=r"(r[0]), "=r"(r[1]), "=r"(r[2]), "=r"(r[3]) : "r"(addr));
}

// mma.sync m16n8k16 bf16 -> f32 accum
__device__ __forceinline__ void mma16816(float c[4], const unsigned a[4],
                                         const unsigned b[2]) {
    asm volatile(
        "mma.sync.aligned.m16n8k16.row.col.f32.bf16.bf16.f32 "
        "{%0,%1,%2,%3}, {%4,%5,%6,%7}, {%8,%9}, {%0,%1,%2,%3};"
        : "+f"(c[0]), "+f"(c[1]), "+f"(c[2]), "+f"(c[3])
        : "r"(a[0]), "r"(a[1]), "r"(a[2]), "r"(a[3]), "r"(b[0]), "r"(b[1]));
}

// ===========================================================================
// Kernel 1: QKV projection (SIMT, unchanged from R2/R3 — converts next round)
// ===========================================================================
#define SPQ 68
__global__ __launch_bounds__(256) void qkv_kernel(
    const float* __restrict__ x,
    const float* __restrict__ Wq, const float* __restrict__ bq,
    const float* __restrict__ Wk, const float* __restrict__ bk,
    const float* __restrict__ Wv, const float* __restrict__ bv)
{
    const float* W;
    const float* bias;
    float* out;
    int sel = blockIdx.y;
    if (sel == 0)      { W = Wq; bias = bq; out = g_q; }
    else if (sel == 1) { W = Wk; bias = bk; out = g_k; }
    else               { W = Wv; bias = bv; out = g_v; }

    __shared__ float Xs[32 * SPQ];
    __shared__ float Ws[32 * SPQ];

    int tid = threadIdx.x;
    int tx = tid & 15;
    int ty = tid >> 4;
    int row0 = blockIdx.x * 64;

    float acc[4][4] = {};

    for (int k0 = 0; k0 < NC; k0 += 32) {
#pragma unroll
        for (int i = 0; i < 8; i++) {
            int idx = tid + i * 256;
            int r = idx >> 5;
            int kk = idx & 31;
            Xs[kk * SPQ + r] = x[(size_t)(row0 + r) * NC + k0 + kk];
            Ws[kk * SPQ + r] = W[(size_t)r * NC + k0 + kk];
        }
        __syncthreads();

#pragma unroll
        for (int kk = 0; kk < 32; kk++) {
            float4 a4 = *(const float4*)&Xs[kk * SPQ + ty * 4];
            float4 b4 = *(const float4*)&Ws[kk * SPQ + tx * 4];
            float a[4] = {a4.x, a4.y, a4.z, a4.w};
            float bb[4] = {b4.x, b4.y, b4.z, b4.w};
#pragma unroll
            for (int i = 0; i < 4; i++)
#pragma unroll
                for (int j = 0; j < 4; j++)
                    acc[i][j] = fmaf(a[i], bb[j], acc[i][j]);
        }
        __syncthreads();
    }

#pragma unroll
    for (int j = 0; j < 4; j++) {
        float bb = bias[tx * 4 + j];
#pragma unroll
        for (int i = 0; i < 4; i++) acc[i][j] += bb;
    }

#pragma unroll
    for (int i = 0; i < 4; i++) {
        float4 val = make_float4(acc[i][0], acc[i][1], acc[i][2], acc[i][3]);
        *(float4*)&out[(size_t)(row0 + ty * 4 + i) * ND + tx * 4] = val;
    }
}

// ===========================================================================
// Kernel 2: flash attention on mma.sync (HMMA bf16x3 split precision).
// grid = (NT/128, NB), 256 threads (8 warps = 4 M-groups x 2 N-halves).
// ===========================================================================
#define SB 72                    // bf16 row stride (144 B -> ldmatrix conflict-free)
#define SM_QHI 0                 // 128 x SB bf16 = 18432 B
#define SM_QLO 18432
#define SM_KHI 36864             // 64 x SB bf16 = 9216 B
#define SM_KLO 46080
#define SM_VHI 55296
#define SM_VLO 64512
#define SM_REDM 73728            // float[256]
#define SM_REDS 74752            // float[256]
#define SM_TOTAL 75776

__global__ __launch_bounds__(256, 1) void attn_kernel(float* __restrict__ out)
{
    extern __shared__ char sm[];
    unsigned smb = smem_to_u32(sm);
    float* redm = (float*)(sm + SM_REDM);
    float* reds = (float*)(sm + SM_REDS);

    int tid = threadIdx.x;
    int lane = tid & 31;
    int wid = tid >> 5;
    int mw = wid & 3;            // M group: rows mw*32 .. +31
    int nh = wid >> 2;           // N half: S cols nh*32 .. +31 (= PV k-half)
    int b = blockIdx.y;
    int q0 = blockIdx.x * BQ;

    const float* q  = g_q + ((size_t)b * NT + q0) * ND;
    const float* kp = g_k + (size_t)b * NT * ND;
    const float* vp = g_v + (size_t)b * NT * ND;

    // ---- stage Q (hi/lo bf16), scale folded in (ref: /D^-0.5 => *8) ----
#pragma unroll
    for (int i = 0; i < 16; i++) {
        int idx = tid + i * 256;          // 4096 float2s
        int rr = idx >> 5;
        int d2 = idx & 31;
        float2 f = *(const float2*)&q[(size_t)rr * ND + d2 * 2];
        unsigned hp, lp;
        split2(f.x * 8.0f, f.y * 8.0f, hp, lp);
        *(unsigned*)(sm + SM_QHI + rr * 144 + d2 * 4) = hp;
        *(unsigned*)(sm + SM_QLO + rr * 144 + d2 * 4) = lp;
    }

    float cO[2][8][4] = {};               // O accum: rows (mi), cols nj*8
    float m_[2][2], l_[2][2];
#pragma unroll
    for (int mi = 0; mi < 2; mi++)
#pragma unroll
        for (int j = 0; j < 2; j++) { m_[mi][j] = -1e30f; l_[mi][j] = 0.0f; }

    for (int kt = 0; kt < NT / BK; kt++) {
        __syncthreads();                  // prior tile's smem reads done; Q ready

        // ---- stage K and V tiles (hi/lo bf16, row-major, stride SB) ----
#pragma unroll
        for (int i = 0; i < 8; i++) {
            int idx = tid + i * 256;      // 2048 float2s
            int rr = idx >> 5;
            int d2 = idx & 31;
            unsigned hp, lp;
            float2 f = *(const float2*)&kp[(size_t)(kt * BK + rr) * ND + d2 * 2];
            split2(f.x, f.y, hp, lp);
            *(unsigned*)(sm + SM_KHI + rr * 144 + d2 * 4) = hp;
            *(unsigned*)(sm + SM_KLO + rr * 144 + d2 * 4) = lp;
            f = *(const float2*)&vp[(size_t)(kt * BK + rr) * ND + d2 * 2];
            split2(f.x, f.y, hp, lp);
            *(unsigned*)(sm + SM_VHI + rr * 144 + d2 * 4) = hp;
            *(unsigned*)(sm + SM_VLO + rr * 144 + d2 * 4) = lp;
        }
        __syncthreads();

        // ---- S = Q K^T, bf16x3: warp tile 32 rows x 32 cols ----
        float cS[2][4][4] = {};
#pragma unroll
        for (int ks = 0; ks < 4; ks++) {  // d k-chunks of 16
            unsigned ah[2][4], al[2][4];
#pragma unroll
            for (int mi = 0; mi < 2; mi++) {
                unsigned qoff = (unsigned)((mw * 32 + mi * 16 + (lane & 15)) * 144 +
                                           (ks * 16 + (lane >> 4) * 8) * 2);
                ldsm4(ah[mi], smb + SM_QHI + qoff);
                ldsm4(al[mi], smb + SM_QLO + qoff);
            }
            unsigned bh[4][2], bl[4][2];
#pragma unroll
            for (int np = 0; np < 2; np++) {
                unsigned koff = (unsigned)((nh * 32 + np * 16 + (lane >> 4) * 8 +
                                            (lane & 7)) * 144 +
                                           (ks * 16 + ((lane >> 3) & 1) * 8) * 2);
                unsigned r[4];
                ldsm4(r, smb + SM_KHI + koff);
                bh[2 * np][0] = r[0]; bh[2 * np][1] = r[1];
                bh[2 * np + 1][0] = r[2]; bh[2 * np + 1][1] = r[3];
                ldsm4(r, smb + SM_KLO + koff);
                bl[2 * np][0] = r[0]; bl[2 * np][1] = r[1];
                bl[2 * np + 1][0] = r[2]; bl[2 * np + 1][1] = r[3];
            }
#pragma unroll
            for (int mi = 0; mi < 2; mi++)
#pragma unroll
                for (int ni = 0; ni < 4; ni++) {
                    mma16816(cS[mi][ni], ah[mi], bh[ni]);
                    mma16816(cS[mi][ni], ah[mi], bl[ni]);
                    mma16816(cS[mi][ni], al[mi], bh[ni]);
                }
        }

        // ---- online softmax (register c-frags; rows = l/4 (+8), quads share) ----
        float alpha[2][2];
#pragma unroll
        for (int mi = 0; mi < 2; mi++)
#pragma unroll
            for (int j = 0; j < 2; j++) {
                float v = -1e30f;
#pragma unroll
                for (int ni = 0; ni < 4; ni++)
                    v = fmaxf(v, fmaxf(cS[mi][ni][2 * j], cS[mi][ni][2 * j + 1]));
                v = fmaxf(v, __shfl_xor_sync(0xffffffffu, v, 1));
                v = fmaxf(v, __shfl_xor_sync(0xffffffffu, v, 2));
                int row = mw * 32 + mi * 16 + j * 8 + (lane >> 2);
                redm[nh * 128 + row] = v;
            }
        __syncthreads();
#pragma unroll
        for (int mi = 0; mi < 2; mi++)
#pragma unroll
            for (int j = 0; j < 2; j++) {
                int row = mw * 32 + mi * 16 + j * 8 + (lane >> 2);
                float cm = fmaxf(redm[row], redm[128 + row]);
                float mn = fmaxf(m_[mi][j], cm);
                alpha[mi][j] = __expf(m_[mi][j] - mn);
                m_[mi][j] = mn;
            }
        // rescale O
#pragma unroll
        for (int mi = 0; mi < 2; mi++)
#pragma unroll
            for (int nj = 0; nj < 8; nj++) {
                cO[mi][nj][0] *= alpha[mi][0];
                cO[mi][nj][1] *= alpha[mi][0];
                cO[mi][nj][2] *= alpha[mi][1];
                cO[mi][nj][3] *= alpha[mi][1];
            }
        // exp + row sums
#pragma unroll
        for (int mi = 0; mi < 2; mi++)
#pragma unroll
            for (int j = 0; j < 2; j++) {
                float s = 0.0f;
#pragma unroll
                for (int ni = 0; ni < 4; ni++) {
                    float e0 = __expf(cS[mi][ni][2 * j] - m_[mi][j]);
                    float e1 = __expf(cS[mi][ni][2 * j + 1] - m_[mi][j]);
                    cS[mi][ni][2 * j] = e0;
                    cS[mi][ni][2 * j + 1] = e1;
                    s += e0 + e1;
                }
                s += __shfl_xor_sync(0xffffffffu, s, 1);
                s += __shfl_xor_sync(0xffffffffu, s, 2);
                int row = mw * 32 + mi * 16 + j * 8 + (lane >> 2);
                reds[nh * 128 + row] = s;
            }
        __syncthreads();
#pragma unroll
        for (int mi = 0; mi < 2; mi++)
#pragma unroll
            for (int j = 0; j < 2; j++) {
                int row = mw * 32 + mi * 16 + j * 8 + (lane >> 2);
                l_[mi][j] = l_[mi][j] * alpha[mi][j] + reds[row] + reds[128 + row];
            }

        // ---- convert P (c-frag -> a-frag identity), hi/lo split ----
        unsigned ph[2][2][4], pl[2][2][4];   // [mi][ks2][reg]
#pragma unroll
        for (int mi = 0; mi < 2; mi++)
#pragma unroll
            for (int ks2 = 0; ks2 < 2; ks2++) {
                split2(cS[mi][2 * ks2][0], cS[mi][2 * ks2][1],
                       ph[mi][ks2][0], pl[mi][ks2][0]);
                split2(cS[mi][2 * ks2][2], cS[mi][2 * ks2][3],
                       ph[mi][ks2][1], pl[mi][ks2][1]);
                split2(cS[mi][2 * ks2 + 1][0], cS[mi][2 * ks2 + 1][1],
                       ph[mi][ks2][2], pl[mi][ks2][2]);
                split2(cS[mi][2 * ks2 + 1][2], cS[mi][2 * ks2 + 1][3],
                       ph[mi][ks2][3], pl[mi][ks2][3]);
            }

        // ---- O += P V over this warp's kv half (k = nh*32 .. +31) ----
#pragma unroll
        for (int ks2 = 0; ks2 < 2; ks2++) {
            unsigned vh[4][4], vl[4][4];     // [npj][reg]: {b0_n, b1_n, b0_n+8, b1_n+8}
#pragma unroll
            for (int npj = 0; npj < 4; npj++) {
                unsigned voff = (unsigned)((nh * 32 + ks2 * 16 + ((lane >> 3) & 1) * 8 +
                                            (lane & 7)) * 144 +
                                           (npj * 16 + (lane >> 4) * 8) * 2);
                ldsm4t(vh[npj], smb + SM_VHI + voff);
                ldsm4t(vl[npj], smb + SM_VLO + voff);
            }
#pragma unroll
            for (int mi = 0; mi < 2; mi++)
#pragma unroll
                for (int nj = 0; nj < 8; nj++) {
                    const unsigned* bbh = &vh[nj >> 1][(nj & 1) * 2];
                    const unsigned* bbl = &vl[nj >> 1][(nj & 1) * 2];
                    mma16816(cO[mi][nj], ph[mi][ks2], bbh);
                    mma16816(cO[mi][nj], ph[mi][ks2], bbl);
                    mma16816(cO[mi][nj], pl[mi][ks2], bbh);
                }
        }
    }

    // ---- epilogue: combine the two k-halves, normalize, store ----
    __syncthreads();                       // all smem reads done; reuse Q region
    float* osm = (float*)sm;               // 128 x 66 fp32 = 33792 B (< Q area)
    if (nh == 1) {
#pragma unroll
        for (int mi = 0; mi < 2; mi++)
#pragma unroll
            for (int nj = 0; nj < 8; nj++) {
                int r0 = mw * 32 + mi * 16 + (lane >> 2);
                int c0 = nj * 8 + 2 * (lane & 3);
                osm[r0 * 66 + c0]       = cO[mi][nj][0];
                osm[r0 * 66 + c0 + 1]   = cO[mi][nj][1];
                osm[(r0 + 8) * 66 + c0]     = cO[mi][nj][2];
                osm[(r0 + 8) * 66 + c0 + 1] = cO[mi][nj][3];
            }
    }
    __syncthreads();
    if (nh == 0) {
#pragma unroll
        for (int mi = 0; mi < 2; mi++) {
            float i0 = 1.0f / l_[mi][0];
            float i1 = 1.0f / l_[mi][1];
#pragma unroll
            for (int nj = 0; nj < 8; nj++) {
                int r0 = mw * 32 + mi * 16 + (lane >> 2);
                int c0 = nj * 8 + 2 * (lane & 3);
                float2 v0 = make_float2(
                    (cO[mi][nj][0] + osm[r0 * 66 + c0]) * i0,
                    (cO[mi][nj][1] + osm[r0 * 66 + c0 + 1]) * i0);
                float2 v1 = make_float2(
                    (cO[mi][nj][2] + osm[(r0 + 8) * 66 + c0]) * i1,
                    (cO[mi][nj][3] + osm[(r0 + 8) * 66 + c0 + 1]) * i1);
                *(float2*)&out[((size_t)b * NT + q0 + r0) * ND + c0] = v0;
                *(float2*)&out[((size_t)b * NT + q0 + r0 + 8) * ND + c0] = v1;
            }
        }
    }
}

// ===========================================================================
extern "C" void kernel_launch(void* const* d_in, const int* in_sizes, int n_in,
                              void* d_out, int out_size)
{
    (void)in_sizes; (void)n_in; (void)out_size;
    const float* x  = (const float*)d_in[0];
    const float* Wq = (const float*)d_in[1];
    const float* bq = (const float*)d_in[2];
    const float* Wk = (const float*)d_in[3];
    const float* bk = (const float*)d_in[4];
    const float* Wv = (const float*)d_in[5];
    const float* bv = (const float*)d_in[6];
    float* out = (float*)d_out;

    qkv_kernel<<<dim3((NB * NT) / 64, 3), 256>>>(x, Wq, bq, Wk, bk, Wv, bv);

    cudaFuncSetAttribute(attn_kernel,
                         cudaFuncAttributeMaxDynamicSharedMemorySize,
                         SM_TOTAL);
    attn_kernel<<<dim3(NT / BQ, NB), 256, SM_TOTAL>>>(out);
}

// round 7
// speedup vs baseline: 2.8575x; 1.5276x over previous
#include <cuda_runtime.h>
#include <cuda_bf16.h>
#include <math.h>

// Problem constants
#define NB 4
#define NT 4096
#define NC 1024
#define ND 64
#define BQ 128          // q rows per CTA (attention)
#define BK 64           // kv tokens per tile (attention)

// Scratch for q, k, v projections (static device globals: allocation-free)
__device__ float g_q[NB * NT * ND];
__device__ float g_k[NB * NT * ND];
__device__ float g_v[NB * NT * ND];
// Pre-split W (packed bf16x2 hi/lo): rows 0-63 Wq, 64-127 Wk, 128-191 Wv
__device__ unsigned g_whi[192 * 512];
__device__ unsigned g_wlo[192 * 512];

// ===========================================================================
// Helpers
// ===========================================================================
__device__ __forceinline__ unsigned smem_to_u32(const void* p) {
    unsigned a;
    asm("{ .reg .u64 t; cvta.to.shared.u64 t, %1; cvt.u32.u64 %0, t; }"
        : "=r"(a) : "l"(p));
    return a;
}

// bf16 hi/lo split of a float pair, packed little-endian (x in low half)
__device__ __forceinline__ void split2(float x, float y, unsigned& hp, unsigned& lp) {
    __nv_bfloat16 hx = __float2bfloat16(x);
    __nv_bfloat16 hy = __float2bfloat16(y);
    float rx = x - __bfloat162float(hx);
    float ry = y - __bfloat162float(hy);
    __nv_bfloat16 lx = __float2bfloat16(rx);
    __nv_bfloat16 ly = __float2bfloat16(ry);
    hp = ((unsigned)__bfloat16_as_ushort(hy) << 16) | __bfloat16_as_ushort(hx);
    lp = ((unsigned)__bfloat16_as_ushort(ly) << 16) | __bfloat16_as_ushort(lx);
}

// ldmatrix x4, non-transposed
__device__ __forceinline__ void ldsm4(unsigned r[4], unsigned addr) {
    asm volatile("ldmatrix.sync.aligned.m8n8.x4.shared.b16 {%0,%1,%2,%3}, [%4];"
        : "=r"(r[0]), "=r"(r[1]), "=r"(r[2]), "=r"(r[3]) : "r"(addr));
}
// ldmatrix x4, transposed (b16)
__device__ __forceinline__ void ldsm4t(unsigned r[4], unsigned addr) {
    asm volatile("ldmatrix.sync.aligned.m8n8.x4.trans.shared.b16 {%0,%1,%2,%3}, [%4];"
        : "=r"(r[0]), "=r"(r[1]), "=r"(r[2]), "=r"(r[3]) : "r"(addr));
}

// mma.sync m16n8k16 bf16 -> f32 accum
__device__ __forceinline__ void mma16816(float c[4], const unsigned a[4],
                                         const unsigned b[2]) {
    asm volatile(
        "mma.sync.aligned.m16n8k16.row.col.f32.bf16.bf16.f32 "
        "{%0,%1,%2,%3}, {%4,%5,%6,%7}, {%8,%9}, {%0,%1,%2,%3};"
        : "+f"(c[0]), "+f"(c[1]), "+f"(c[2]), "+f"(c[3])
        : "r"(a[0]), "r"(a[1]), "r"(a[2]), "r"(a[3]), "r"(b[0]), "r"(b[1]));
}

// ===========================================================================
// Kernel 0: W pre-split (fp32 -> packed bf16 hi/lo), 192 x 1024 elements.
// ===========================================================================
__global__ __launch_bounds__(256) void wsplit_kernel(
    const float* __restrict__ Wq, const float* __restrict__ Wk,
    const float* __restrict__ Wv)
{
    int idx = blockIdx.x * 256 + threadIdx.x;   // 0..98303 (uint pairs)
    int row = idx >> 9;                         // 0..191
    int d2 = idx & 511;
    const float* W = (row < 64) ? Wq : (row < 128 ? Wk : Wv);
    int r = row & 63;
    float2 f = *(const float2*)&W[(size_t)r * NC + d2 * 2];
    unsigned hp, lp;
    split2(f.x, f.y, hp, lp);
    g_whi[idx] = hp;
    g_wlo[idx] = lp;
}

// ===========================================================================
// Kernel 1: fused QKV projection on mma.sync (bf16x3).
// out[r][n] = sum_k x[r][k] * W[n][k] + b[n], N = 192 (q|k|v).
// grid = 128 (M tiles of 128), 256 threads (8 warps = 4 M x 2 N-halves of 96).
// ===========================================================================
#define QK_XHI 0            // 128 x 72 bf16 = 18432 B
#define QK_XLO 18432
#define QK_WHI 36864        // 192 x 72 bf16 = 27648 B
#define QK_WLO 64512
#define QK_TOTAL 92160

__global__ __launch_bounds__(256, 1) void qkv_kernel(
    const float* __restrict__ x,
    const float* __restrict__ bq, const float* __restrict__ bk,
    const float* __restrict__ bv)
{
    extern __shared__ char sm[];
    unsigned smb = smem_to_u32(sm);

    int tid = threadIdx.x;
    int lane = tid & 31;
    int wid = tid >> 5;
    int mw = wid & 3;           // rows mw*32 .. +31
    int nh = wid >> 2;          // cols nh*96 .. +95
    int row0 = blockIdx.x * 128;

    float cO[2][12][4] = {};

    for (int kc = 0; kc < 16; kc++) {
        if (kc) __syncthreads();            // prior chunk's reads done

        // ---- stage X chunk (128 rows x 64 k), split to hi/lo ----
#pragma unroll
        for (int i = 0; i < 16; i++) {
            int idx = tid + i * 256;        // 4096 float2s
            int rr = idx >> 5;
            int d2 = idx & 31;
            float2 f = *(const float2*)&x[(size_t)(row0 + rr) * NC + kc * 64 + d2 * 2];
            unsigned hp, lp;
            split2(f.x, f.y, hp, lp);
            *(unsigned*)(sm + QK_XHI + rr * 144 + d2 * 4) = hp;
            *(unsigned*)(sm + QK_XLO + rr * 144 + d2 * 4) = lp;
        }
        // ---- stage W chunk (192 rows x 64 k), already split ----
#pragma unroll
        for (int i = 0; i < 24; i++) {
            int idx = tid + i * 256;        // 6144 uints
            int rr = idx >> 5;
            int d2 = idx & 31;
            int gsrc = rr * 512 + kc * 32 + d2;
            *(unsigned*)(sm + QK_WHI + rr * 144 + d2 * 4) = g_whi[gsrc];
            *(unsigned*)(sm + QK_WLO + rr * 144 + d2 * 4) = g_wlo[gsrc];
        }
        __syncthreads();

        // ---- MMA: warp tile 32 rows x 96 cols, bf16x3 ----
#pragma unroll
        for (int ks = 0; ks < 4; ks++) {
            unsigned ah[2][4], al[2][4];
#pragma unroll
            for (int mi = 0; mi < 2; mi++) {
                unsigned xoff = (unsigned)((mw * 32 + mi * 16 + (lane & 15)) * 144 +
                                           (ks * 16 + (lane >> 4) * 8) * 2);
                ldsm4(ah[mi], smb + QK_XHI + xoff);
                ldsm4(al[mi], smb + QK_XLO + xoff);
            }
            unsigned bh[12][2], bl[12][2];
#pragma unroll
            for (int np = 0; np < 6; np++) {
                unsigned woff = (unsigned)((nh * 96 + np * 16 + (lane >> 4) * 8 +
                                            (lane & 7)) * 144 +
                                           (ks * 16 + ((lane >> 3) & 1) * 8) * 2);
                unsigned r[4];
                ldsm4(r, smb + QK_WHI + woff);
                bh[2 * np][0] = r[0]; bh[2 * np][1] = r[1];
                bh[2 * np + 1][0] = r[2]; bh[2 * np + 1][1] = r[3];
                ldsm4(r, smb + QK_WLO + woff);
                bl[2 * np][0] = r[0]; bl[2 * np][1] = r[1];
                bl[2 * np + 1][0] = r[2]; bl[2 * np + 1][1] = r[3];
            }
#pragma unroll
            for (int mi = 0; mi < 2; mi++)
#pragma unroll
                for (int nj = 0; nj < 12; nj++) {
                    mma16816(cO[mi][nj], ah[mi], bh[nj]);
                    mma16816(cO[mi][nj], ah[mi], bl[nj]);
                    mma16816(cO[mi][nj], al[mi], bh[nj]);
                }
        }
    }

    // ---- epilogue: add bias, scatter to g_q/g_k/g_v ----
#pragma unroll
    for (int mi = 0; mi < 2; mi++)
#pragma unroll
        for (int nj = 0; nj < 12; nj++) {
            int gc = nh * 96 + nj * 8 + 2 * (lane & 3);   // global col 0..190
            float* dst;
            const float* bias;
            int col;
            if (gc < 64)       { dst = g_q; bias = bq; col = gc; }
            else if (gc < 128) { dst = g_k; bias = bk; col = gc - 64; }
            else               { dst = g_v; bias = bv; col = gc - 128; }
            int r0 = row0 + mw * 32 + mi * 16 + (lane >> 2);
            float b0 = __ldg(&bias[col]);
            float b1 = __ldg(&bias[col + 1]);
            *(float2*)&dst[(size_t)r0 * ND + col] =
                make_float2(cO[mi][nj][0] + b0, cO[mi][nj][1] + b1);
            *(float2*)&dst[(size_t)(r0 + 8) * ND + col] =
                make_float2(cO[mi][nj][2] + b0, cO[mi][nj][3] + b1);
        }
}

// ===========================================================================
// Kernel 2: flash attention on mma.sync (HMMA bf16x3) — unchanged from R4.
// grid = (NT/128, NB), 256 threads (8 warps = 4 M-groups x 2 N-halves).
// ===========================================================================
#define SB 72                    // bf16 row stride (144 B -> ldmatrix conflict-free)
#define SM_QHI 0                 // 128 x SB bf16 = 18432 B
#define SM_QLO 18432
#define SM_KHI 36864             // 64 x SB bf16 = 9216 B
#define SM_KLO 46080
#define SM_VHI 55296
#define SM_VLO 64512
#define SM_REDM 73728            // float[256]
#define SM_REDS 74752            // float[256]
#define SM_TOTAL 75776

__global__ __launch_bounds__(256, 1) void attn_kernel(float* __restrict__ out)
{
    extern __shared__ char sm[];
    unsigned smb = smem_to_u32(sm);
    float* redm = (float*)(sm + SM_REDM);
    float* reds = (float*)(sm + SM_REDS);

    int tid = threadIdx.x;
    int lane = tid & 31;
    int wid = tid >> 5;
    int mw = wid & 3;            // M group: rows mw*32 .. +31
    int nh = wid >> 2;           // N half: S cols nh*32 .. +31 (= PV k-half)
    int b = blockIdx.y;
    int q0 = blockIdx.x * BQ;

    const float* q  = g_q + ((size_t)b * NT + q0) * ND;
    const float* kp = g_k + (size_t)b * NT * ND;
    const float* vp = g_v + (size_t)b * NT * ND;

    // ---- stage Q (hi/lo bf16), scale folded in (ref: /D^-0.5 => *8) ----
#pragma unroll
    for (int i = 0; i < 16; i++) {
        int idx = tid + i * 256;          // 4096 float2s
        int rr = idx >> 5;
        int d2 = idx & 31;
        float2 f = *(const float2*)&q[(size_t)rr * ND + d2 * 2];
        unsigned hp, lp;
        split2(f.x * 8.0f, f.y * 8.0f, hp, lp);
        *(unsigned*)(sm + SM_QHI + rr * 144 + d2 * 4) = hp;
        *(unsigned*)(sm + SM_QLO + rr * 144 + d2 * 4) = lp;
    }

    float cO[2][8][4] = {};               // O accum: rows (mi), cols nj*8
    float m_[2][2], l_[2][2];
#pragma unroll
    for (int mi = 0; mi < 2; mi++)
#pragma unroll
        for (int j = 0; j < 2; j++) { m_[mi][j] = -1e30f; l_[mi][j] = 0.0f; }

    for (int kt = 0; kt < NT / BK; kt++) {
        __syncthreads();                  // prior tile's smem reads done; Q ready

        // ---- stage K and V tiles (hi/lo bf16, row-major, stride SB) ----
#pragma unroll
        for (int i = 0; i < 8; i++) {
            int idx = tid + i * 256;      // 2048 float2s
            int rr = idx >> 5;
            int d2 = idx & 31;
            unsigned hp, lp;
            float2 f = *(const float2*)&kp[(size_t)(kt * BK + rr) * ND + d2 * 2];
            split2(f.x, f.y, hp, lp);
            *(unsigned*)(sm + SM_KHI + rr * 144 + d2 * 4) = hp;
            *(unsigned*)(sm + SM_KLO + rr * 144 + d2 * 4) = lp;
            f = *(const float2*)&vp[(size_t)(kt * BK + rr) * ND + d2 * 2];
            split2(f.x, f.y, hp, lp);
            *(unsigned*)(sm + SM_VHI + rr * 144 + d2 * 4) = hp;
            *(unsigned*)(sm + SM_VLO + rr * 144 + d2 * 4) = lp;
        }
        __syncthreads();

        // ---- S = Q K^T, bf16x3: warp tile 32 rows x 32 cols ----
        float cS[2][4][4] = {};
#pragma unroll
        for (int ks = 0; ks < 4; ks++) {  // d k-chunks of 16
            unsigned ah[2][4], al[2][4];
#pragma unroll
            for (int mi = 0; mi < 2; mi++) {
                unsigned qoff = (unsigned)((mw * 32 + mi * 16 + (lane & 15)) * 144 +
                                           (ks * 16 + (lane >> 4) * 8) * 2);
                ldsm4(ah[mi], smb + SM_QHI + qoff);
                ldsm4(al[mi], smb + SM_QLO + qoff);
            }
            unsigned bh[4][2], bl[4][2];
#pragma unroll
            for (int np = 0; np < 2; np++) {
                unsigned koff = (unsigned)((nh * 32 + np * 16 + (lane >> 4) * 8 +
                                            (lane & 7)) * 144 +
                                           (ks * 16 + ((lane >> 3) & 1) * 8) * 2);
                unsigned r[4];
                ldsm4(r, smb + SM_KHI + koff);
                bh[2 * np][0] = r[0]; bh[2 * np][1] = r[1];
                bh[2 * np + 1][0] = r[2]; bh[2 * np + 1][1] = r[3];
                ldsm4(r, smb + SM_KLO + koff);
                bl[2 * np][0] = r[0]; bl[2 * np][1] = r[1];
                bl[2 * np + 1][0] = r[2]; bl[2 * np + 1][1] = r[3];
            }
#pragma unroll
            for (int mi = 0; mi < 2; mi++)
#pragma unroll
                for (int ni = 0; ni < 4; ni++) {
                    mma16816(cS[mi][ni], ah[mi], bh[ni]);
                    mma16816(cS[mi][ni], ah[mi], bl[ni]);
                    mma16816(cS[mi][ni], al[mi], bh[ni]);
                }
        }

        // ---- online softmax (register c-frags; rows = l/4 (+8), quads share) ----
        float alpha[2][2];
#pragma unroll
        for (int mi = 0; mi < 2; mi++)
#pragma unroll
            for (int j = 0; j < 2; j++) {
                float v = -1e30f;
#pragma unroll
                for (int ni = 0; ni < 4; ni++)
                    v = fmaxf(v, fmaxf(cS[mi][ni][2 * j], cS[mi][ni][2 * j + 1]));
                v = fmaxf(v, __shfl_xor_sync(0xffffffffu, v, 1));
                v = fmaxf(v, __shfl_xor_sync(0xffffffffu, v, 2));
                int row = mw * 32 + mi * 16 + j * 8 + (lane >> 2);
                redm[nh * 128 + row] = v;
            }
        __syncthreads();
#pragma unroll
        for (int mi = 0; mi < 2; mi++)
#pragma unroll
            for (int j = 0; j < 2; j++) {
                int row = mw * 32 + mi * 16 + j * 8 + (lane >> 2);
                float cm = fmaxf(redm[row], redm[128 + row]);
                float mn = fmaxf(m_[mi][j], cm);
                alpha[mi][j] = __expf(m_[mi][j] - mn);
                m_[mi][j] = mn;
            }
        // rescale O
#pragma unroll
        for (int mi = 0; mi < 2; mi++)
#pragma unroll
            for (int nj = 0; nj < 8; nj++) {
                cO[mi][nj][0] *= alpha[mi][0];
                cO[mi][nj][1] *= alpha[mi][0];
                cO[mi][nj][2] *= alpha[mi][1];
                cO[mi][nj][3] *= alpha[mi][1];
            }
        // exp + row sums
#pragma unroll
        for (int mi = 0; mi < 2; mi++)
#pragma unroll
            for (int j = 0; j < 2; j++) {
                float s = 0.0f;
#pragma unroll
                for (int ni = 0; ni < 4; ni++) {
                    float e0 = __expf(cS[mi][ni][2 * j] - m_[mi][j]);
                    float e1 = __expf(cS[mi][ni][2 * j + 1] - m_[mi][j]);
                    cS[mi][ni][2 * j] = e0;
                    cS[mi][ni][2 * j + 1] = e1;
                    s += e0 + e1;
                }
                s += __shfl_xor_sync(0xffffffffu, s, 1);
                s += __shfl_xor_sync(0xffffffffu, s, 2);
                int row = mw * 32 + mi * 16 + j * 8 + (lane >> 2);
                reds[nh * 128 + row] = s;
            }
        __syncthreads();
#pragma unroll
        for (int mi = 0; mi < 2; mi++)
#pragma unroll
            for (int j = 0; j < 2; j++) {
                int row = mw * 32 + mi * 16 + j * 8 + (lane >> 2);
                l_[mi][j] = l_[mi][j] * alpha[mi][j] + reds[row] + reds[128 + row];
            }

        // ---- convert P (c-frag -> a-frag identity), hi/lo split ----
        unsigned ph[2][2][4], pl[2][2][4];   // [mi][ks2][reg]
#pragma unroll
        for (int mi = 0; mi < 2; mi++)
#pragma unroll
            for (int ks2 = 0; ks2 < 2; ks2++) {
                split2(cS[mi][2 * ks2][0], cS[mi][2 * ks2][1],
                       ph[mi][ks2][0], pl[mi][ks2][0]);
                split2(cS[mi][2 * ks2][2], cS[mi][2 * ks2][3],
                       ph[mi][ks2][1], pl[mi][ks2][1]);
                split2(cS[mi][2 * ks2 + 1][0], cS[mi][2 * ks2 + 1][1],
                       ph[mi][ks2][2], pl[mi][ks2][2]);
                split2(cS[mi][2 * ks2 + 1][2], cS[mi][2 * ks2 + 1][3],
                       ph[mi][ks2][3], pl[mi][ks2][3]);
            }

        // ---- O += P V over this warp's kv half (k = nh*32 .. +31) ----
#pragma unroll
        for (int ks2 = 0; ks2 < 2; ks2++) {
            unsigned vh[4][4], vl[4][4];     // [npj][reg]: {b0_n, b1_n, b0_n+8, b1_n+8}
#pragma unroll
            for (int npj = 0; npj < 4; npj++) {
                unsigned voff = (unsigned)((nh * 32 + ks2 * 16 + ((lane >> 3) & 1) * 8 +
                                            (lane & 7)) * 144 +
                                           (npj * 16 + (lane >> 4) * 8) * 2);
                ldsm4t(vh[npj], smb + SM_VHI + voff);
                ldsm4t(vl[npj], smb + SM_VLO + voff);
            }
#pragma unroll
            for (int mi = 0; mi < 2; mi++)
#pragma unroll
                for (int nj = 0; nj < 8; nj++) {
                    const unsigned* bbh = &vh[nj >> 1][(nj & 1) * 2];
                    const unsigned* bbl = &vl[nj >> 1][(nj & 1) * 2];
                    mma16816(cO[mi][nj], ph[mi][ks2], bbh);
                    mma16816(cO[mi][nj], ph[mi][ks2], bbl);
                    mma16816(cO[mi][nj], pl[mi][ks2], bbh);
                }
        }
    }

    // ---- epilogue: combine the two k-halves, normalize, store ----
    __syncthreads();                       // all smem reads done; reuse Q region
    float* osm = (float*)sm;               // 128 x 66 fp32 = 33792 B (< Q area)
    if (nh == 1) {
#pragma unroll
        for (int mi = 0; mi < 2; mi++)
#pragma unroll
            for (int nj = 0; nj < 8; nj++) {
                int r0 = mw * 32 + mi * 16 + (lane >> 2);
                int c0 = nj * 8 + 2 * (lane & 3);
                osm[r0 * 66 + c0]       = cO[mi][nj][0];
                osm[r0 * 66 + c0 + 1]   = cO[mi][nj][1];
                osm[(r0 + 8) * 66 + c0]     = cO[mi][nj][2];
                osm[(r0 + 8) * 66 + c0 + 1] = cO[mi][nj][3];
            }
    }
    __syncthreads();
    if (nh == 0) {
#pragma unroll
        for (int mi = 0; mi < 2; mi++) {
            float i0 = 1.0f / l_[mi][0];
            float i1 = 1.0f / l_[mi][1];
#pragma unroll
            for (int nj = 0; nj < 8; nj++) {
                int r0 = mw * 32 + mi * 16 + (lane >> 2);
                int c0 = nj * 8 + 2 * (lane & 3);
                float2 v0 = make_float2(
                    (cO[mi][nj][0] + osm[r0 * 66 + c0]) * i0,
                    (cO[mi][nj][1] + osm[r0 * 66 + c0 + 1]) * i0);
                float2 v1 = make_float2(
                    (cO[mi][nj][2] + osm[(r0 + 8) * 66 + c0]) * i1,
                    (cO[mi][nj][3] + osm[(r0 + 8) * 66 + c0 + 1]) * i1);
                *(float2*)&out[((size_t)b * NT + q0 + r0) * ND + c0] = v0;
                *(float2*)&out[((size_t)b * NT + q0 + r0 + 8) * ND + c0] = v1;
            }
        }
    }
}

// ===========================================================================
extern "C" void kernel_launch(void* const* d_in, const int* in_sizes, int n_in,
                              void* d_out, int out_size)
{
    (void)in_sizes; (void)n_in; (void)out_size;
    const float* x  = (const float*)d_in[0];
    const float* Wq = (const float*)d_in[1];
    const float* bq = (const float*)d_in[2];
    const float* Wk = (const float*)d_in[3];
    const float* bk = (const float*)d_in[4];
    const float* Wv = (const float*)d_in[5];
    const float* bv = (const float*)d_in[6];
    float* out = (float*)d_out;

    // 0: pre-split W into bf16 hi/lo (192*512 uint pairs)
    wsplit_kernel<<<384, 256>>>(Wq, Wk, Wv);

    // 1: fused QKV projection (tensor cores)
    cudaFuncSetAttribute(qkv_kernel,
                         cudaFuncAttributeMaxDynamicSharedMemorySize,
                         QK_TOTAL);
    qkv_kernel<<<(NB * NT) / 128, 256, QK_TOTAL>>>(x, bq, bk, bv);

    // 2: flash attention (tensor cores)
    cudaFuncSetAttribute(attn_kernel,
                         cudaFuncAttributeMaxDynamicSharedMemorySize,
                         SM_TOTAL);
    attn_kernel<<<dim3(NT / BQ, NB), 256, SM_TOTAL>>>(out);
}

// round 9
// speedup vs baseline: 3.5067x; 1.2272x over previous
#include <cuda_runtime.h>
#include <cuda_bf16.h>
#include <math.h>

// Problem constants
#define NB 4
#define NT 4096
#define NC 1024
#define ND 64
#define BQ 64           // q rows per CTA (attention)
#define BK 64           // kv tokens per tile (attention)

// Pre-split projections (packed bf16x2 hi/lo, 32 uints per token row).
// Q is stored pre-scaled by 8 (score scale, exact power of 2).
__device__ unsigned g_qhi[NB * NT * 32];
__device__ unsigned g_qlo[NB * NT * 32];
__device__ unsigned g_khi[NB * NT * 32];
__device__ unsigned g_klo[NB * NT * 32];
__device__ unsigned g_vhi[NB * NT * 32];
__device__ unsigned g_vlo[NB * NT * 32];
// Pre-split W (packed bf16x2 hi/lo): rows 0-63 Wq, 64-127 Wk, 128-191 Wv
__device__ unsigned g_whi[192 * 512];
__device__ unsigned g_wlo[192 * 512];

// ===========================================================================
// Helpers
// ===========================================================================
__device__ __forceinline__ unsigned smem_to_u32(const void* p) {
    unsigned a;
    asm("{ .reg .u64 t; cvta.to.shared.u64 t, %1; cvt.u32.u64 %0, t; }"
        : "=r"(a) : "l"(p));
    return a;
}

// bf16 hi/lo split of a float pair, packed little-endian (x in low half)
__device__ __forceinline__ void split2(float x, float y, unsigned& hp, unsigned& lp) {
    __nv_bfloat16 hx = __float2bfloat16(x);
    __nv_bfloat16 hy = __float2bfloat16(y);
    float rx = x - __bfloat162float(hx);
    float ry = y - __bfloat162float(hy);
    __nv_bfloat16 lx = __float2bfloat16(rx);
    __nv_bfloat16 ly = __float2bfloat16(ry);
    hp = ((unsigned)__bfloat16_as_ushort(hy) << 16) | __bfloat16_as_ushort(hx);
    lp = ((unsigned)__bfloat16_as_ushort(ly) << 16) | __bfloat16_as_ushort(lx);
}

// ldmatrix x4, non-transposed
__device__ __forceinline__ void ldsm4(unsigned r[4], unsigned addr) {
    asm volatile("ldmatrix.sync.aligned.m8n8.x4.shared.b16 {%0,%1,%2,%3}, [%4];"
        : "=r"(r[0]), "=r"(r[1]), "=r"(r[2]), "=r"(r[3]) : "r"(addr));
}
// ldmatrix x4, transposed (b16)
__device__ __forceinline__ void ldsm4t(unsigned r[4], unsigned addr) {
    asm volatile("ldmatrix.sync.aligned.m8n8.x4.trans.shared.b16 {%0,%1,%2,%3}, [%4];"
        : "=r"(r[0]), "=r"(r[1]), "=r"(r[2]), "=r"(r[3]) : "r"(addr));
}

// mma.sync m16n8k16 bf16 -> f32 accum
__device__ __forceinline__ void mma16816(float c[4], const unsigned a[4],
                                         const unsigned b[2]) {
    asm volatile(
        "mma.sync.aligned.m16n8k16.row.col.f32.bf16.bf16.f32 "
        "{%0,%1,%2,%3}, {%4,%5,%6,%7}, {%8,%9}, {%0,%1,%2,%3};"
        : "+f"(c[0]), "+f"(c[1]), "+f"(c[2]), "+f"(c[3])
        : "r"(a[0]), "r"(a[1]), "r"(a[2]), "r"(a[3]), "r"(b[0]), "r"(b[1]));
}

// cp.async 16B, L1-bypass
__device__ __forceinline__ void cp16(unsigned dst, const unsigned* src) {
    asm volatile("cp.async.cg.shared.global [%0], [%1], 16;"
        :: "r"(dst), "l"(src));
}
#define CP_COMMIT() asm volatile("cp.async.commit_group;" ::: "memory")
#define CP_WAIT(n)  asm volatile("cp.async.wait_group %0;" :: "n"(n) : "memory")

// ===========================================================================
// Kernel 0: W pre-split (fp32 -> packed bf16 hi/lo), 192 x 1024 elements.
// ===========================================================================
__global__ __launch_bounds__(256) void wsplit_kernel(
    const float* __restrict__ Wq, const float* __restrict__ Wk,
    const float* __restrict__ Wv)
{
    int idx = blockIdx.x * 256 + threadIdx.x;   // 0..98303 (uint pairs)
    int row = idx >> 9;                         // 0..191
    int d2 = idx & 511;
    const float* W = (row < 64) ? Wq : (row < 128 ? Wk : Wv);
    int r = row & 63;
    float2 f = *(const float2*)&W[(size_t)r * NC + d2 * 2];
    unsigned hp, lp;
    split2(f.x, f.y, hp, lp);
    g_whi[idx] = hp;
    g_wlo[idx] = lp;
}

// ===========================================================================
// Kernel 1: fused QKV projection on mma.sync (bf16x3).
// Epilogue writes pre-split packed bf16 hi/lo directly (Q scaled by 8).
// grid = 128 (M tiles of 128), 256 threads (8 warps = 4 M x 2 N-halves of 96).
// ===========================================================================
#define QK_XHI 0            // 128 x 72 bf16 = 18432 B
#define QK_XLO 18432
#define QK_WHI 36864        // 192 x 72 bf16 = 27648 B
#define QK_WLO 64512
#define QK_TOTAL 92160

__global__ __launch_bounds__(256, 1) void qkv_kernel(
    const float* __restrict__ x,
    const float* __restrict__ bq, const float* __restrict__ bk,
    const float* __restrict__ bv)
{
    extern __shared__ char sm[];
    unsigned smb = smem_to_u32(sm);

    int tid = threadIdx.x;
    int lane = tid & 31;
    int wid = tid >> 5;
    int mw = wid & 3;           // rows mw*32 .. +31
    int nh = wid >> 2;          // cols nh*96 .. +95
    int row0 = blockIdx.x * 128;

    float cO[2][12][4] = {};

    for (int kc = 0; kc < 16; kc++) {
        if (kc) __syncthreads();            // prior chunk's reads done

        // ---- stage X chunk (128 rows x 64 k), split to hi/lo ----
#pragma unroll
        for (int i = 0; i < 16; i++) {
            int idx = tid + i * 256;        // 4096 float2s
            int rr = idx >> 5;
            int d2 = idx & 31;
            float2 f = *(const float2*)&x[(size_t)(row0 + rr) * NC + kc * 64 + d2 * 2];
            unsigned hp, lp;
            split2(f.x, f.y, hp, lp);
            *(unsigned*)(sm + QK_XHI + rr * 144 + d2 * 4) = hp;
            *(unsigned*)(sm + QK_XLO + rr * 144 + d2 * 4) = lp;
        }
        // ---- stage W chunk (192 rows x 64 k), already split ----
#pragma unroll
        for (int i = 0; i < 24; i++) {
            int idx = tid + i * 256;        // 6144 uints
            int rr = idx >> 5;
            int d2 = idx & 31;
            int gsrc = rr * 512 + kc * 32 + d2;
            *(unsigned*)(sm + QK_WHI + rr * 144 + d2 * 4) = g_whi[gsrc];
            *(unsigned*)(sm + QK_WLO + rr * 144 + d2 * 4) = g_wlo[gsrc];
        }
        __syncthreads();

        // ---- MMA: warp tile 32 rows x 96 cols, bf16x3 ----
#pragma unroll
        for (int ks = 0; ks < 4; ks++) {
            unsigned ah[2][4], al[2][4];
#pragma unroll
            for (int mi = 0; mi < 2; mi++) {
                unsigned xoff = (unsigned)((mw * 32 + mi * 16 + (lane & 15)) * 144 +
                                           (ks * 16 + (lane >> 4) * 8) * 2);
                ldsm4(ah[mi], smb + QK_XHI + xoff);
                ldsm4(al[mi], smb + QK_XLO + xoff);
            }
            unsigned bh[12][2], bl[12][2];
#pragma unroll
            for (int np = 0; np < 6; np++) {
                unsigned woff = (unsigned)((nh * 96 + np * 16 + (lane >> 4) * 8 +
                                            (lane & 7)) * 144 +
                                           (ks * 16 + ((lane >> 3) & 1) * 8) * 2);
                unsigned r[4];
                ldsm4(r, smb + QK_WHI + woff);
                bh[2 * np][0] = r[0]; bh[2 * np][1] = r[1];
                bh[2 * np + 1][0] = r[2]; bh[2 * np + 1][1] = r[3];
                ldsm4(r, smb + QK_WLO + woff);
                bl[2 * np][0] = r[0]; bl[2 * np][1] = r[1];
                bl[2 * np + 1][0] = r[2]; bl[2 * np + 1][1] = r[3];
            }
#pragma unroll
            for (int mi = 0; mi < 2; mi++)
#pragma unroll
                for (int nj = 0; nj < 12; nj++) {
                    mma16816(cO[mi][nj], ah[mi], bh[nj]);
                    mma16816(cO[mi][nj], ah[mi], bl[nj]);
                    mma16816(cO[mi][nj], al[mi], bh[nj]);
                }
        }
    }

    // ---- epilogue: add bias, split to bf16 hi/lo, write packed ----
#pragma unroll
    for (int mi = 0; mi < 2; mi++)
#pragma unroll
        for (int nj = 0; nj < 12; nj++) {
            int gc = nh * 96 + nj * 8 + 2 * (lane & 3);   // global col, even
            unsigned *dhi, *dlo;
            const float* bias;
            int col;
            float scale;
            if (gc < 64)       { dhi = g_qhi; dlo = g_qlo; bias = bq; col = gc; scale = 8.0f; }
            else if (gc < 128) { dhi = g_khi; dlo = g_klo; bias = bk; col = gc - 64; scale = 1.0f; }
            else               { dhi = g_vhi; dlo = g_vlo; bias = bv; col = gc - 128; scale = 1.0f; }
            int r0 = row0 + mw * 32 + mi * 16 + (lane >> 2);
            float b0 = __ldg(&bias[col]);
            float b1 = __ldg(&bias[col + 1]);
            unsigned hp, lp;
            split2((cO[mi][nj][0] + b0) * scale, (cO[mi][nj][1] + b1) * scale, hp, lp);
            dhi[(size_t)r0 * 32 + col / 2] = hp;
            dlo[(size_t)r0 * 32 + col / 2] = lp;
            split2((cO[mi][nj][2] + b0) * scale, (cO[mi][nj][3] + b1) * scale, hp, lp);
            dhi[(size_t)(r0 + 8) * 32 + col / 2] = hp;
            dlo[(size_t)(r0 + 8) * 32 + col / 2] = lp;
        }
}

// ===========================================================================
// Kernel 2: flash attention on mma.sync (HMMA bf16x3).
// grid = (NT/64, NB), 128 threads (4 warps = 2 M-groups x 2 N-halves).
// 2 CTAs/SM; K/V tiles double-buffered via cp.async.
// ===========================================================================
#define AT_QHI 0                 // 64 x 144 B = 9216
#define AT_QLO 9216
#define AT_KV  18432             // 2 stages x 36864 (khi,klo,vhi,vlo @ 9216 each)
#define AT_STG 36864
#define AT_REDM 92160            // float[128]
#define AT_REDS 92672            // float[128]
#define AT_TOTAL 93184

__device__ __forceinline__ void stage_kv(unsigned smb, int s, int tid, int kt,
    const unsigned* khi, const unsigned* klo,
    const unsigned* vhi, const unsigned* vlo)
{
    unsigned base = smb + AT_KV + s * AT_STG;
    const unsigned* gs[4] = {khi, klo, vhi, vlo};
#pragma unroll
    for (int a = 0; a < 4; a++)
#pragma unroll
        for (int i = 0; i < 4; i++) {
            int idx = tid + i * 128;      // 0..511
            int rr = idx >> 3;
            int c = idx & 7;
            cp16(base + a * 9216 + rr * 144 + c * 16,
                 gs[a] + (size_t)(kt * BK + rr) * 32 + c * 4);
        }
}

__global__ __launch_bounds__(128, 2) void attn_kernel(float* __restrict__ out)
{
    extern __shared__ char sm[];
    unsigned smb = smem_to_u32(sm);
    float* redm = (float*)(sm + AT_REDM);
    float* reds = (float*)(sm + AT_REDS);

    int tid = threadIdx.x;
    int lane = tid & 31;
    int wid = tid >> 5;
    int mw = wid & 1;            // M group: rows mw*32 .. +31
    int nh = wid >> 1;           // N half: S cols nh*32 .. +31 (= PV k-half)
    int b = blockIdx.y;
    int q0 = blockIdx.x * BQ;

    const unsigned* qhi = g_qhi + (size_t)b * NT * 32;
    const unsigned* qlo = g_qlo + (size_t)b * NT * 32;
    const unsigned* khi = g_khi + (size_t)b * NT * 32;
    const unsigned* klo = g_klo + (size_t)b * NT * 32;
    const unsigned* vhi = g_vhi + (size_t)b * NT * 32;
    const unsigned* vlo = g_vlo + (size_t)b * NT * 32;

    // ---- stage Q (already split & scaled) + first K/V tile ----
    {
        const unsigned* qs[2] = {qhi, qlo};
#pragma unroll
        for (int a = 0; a < 2; a++)
#pragma unroll
            for (int i = 0; i < 4; i++) {
                int idx = tid + i * 128;
                int rr = idx >> 3;
                int c = idx & 7;
                cp16(smb + a * 9216 + rr * 144 + c * 16,
                     qs[a] + (size_t)(q0 + rr) * 32 + c * 4);
            }
    }
    stage_kv(smb, 0, tid, 0, khi, klo, vhi, vlo);
    CP_COMMIT();

    float cO[2][8][4] = {};               // O accum: rows (mi), cols nj*8
    float m_[2][2], l_[2][2];
#pragma unroll
    for (int mi = 0; mi < 2; mi++)
#pragma unroll
        for (int j = 0; j < 2; j++) { m_[mi][j] = -1e30f; l_[mi][j] = 0.0f; }

    for (int kt = 0; kt < NT / BK; kt++) {
        int s = kt & 1;
        unsigned kb = smb + AT_KV + s * AT_STG;          // khi base
        if (kt + 1 < NT / BK) {
            stage_kv(smb, s ^ 1, tid, kt + 1, khi, klo, vhi, vlo);
            CP_COMMIT();
            CP_WAIT(1);
        } else {
            CP_WAIT(0);
        }
        __syncthreads();

        // ---- S = Q K^T, bf16x3: warp tile 32 rows x 32 cols ----
        float cS[2][4][4] = {};
#pragma unroll
        for (int ks = 0; ks < 4; ks++) {  // d k-chunks of 16
            unsigned ah[2][4], al[2][4];
#pragma unroll
            for (int mi = 0; mi < 2; mi++) {
                unsigned qoff = (unsigned)((mw * 32 + mi * 16 + (lane & 15)) * 144 +
                                           (ks * 16 + (lane >> 4) * 8) * 2);
                ldsm4(ah[mi], smb + AT_QHI + qoff);
                ldsm4(al[mi], smb + AT_QLO + qoff);
            }
            unsigned bh[4][2], bl[4][2];
#pragma unroll
            for (int np = 0; np < 2; np++) {
                unsigned koff = (unsigned)((nh * 32 + np * 16 + (lane >> 4) * 8 +
                                            (lane & 7)) * 144 +
                                           (ks * 16 + ((lane >> 3) & 1) * 8) * 2);
                unsigned r[4];
                ldsm4(r, kb + koff);
                bh[2 * np][0] = r[0]; bh[2 * np][1] = r[1];
                bh[2 * np + 1][0] = r[2]; bh[2 * np + 1][1] = r[3];
                ldsm4(r, kb + 9216 + koff);
                bl[2 * np][0] = r[0]; bl[2 * np][1] = r[1];
                bl[2 * np + 1][0] = r[2]; bl[2 * np + 1][1] = r[3];
            }
#pragma unroll
            for (int mi = 0; mi < 2; mi++)
#pragma unroll
                for (int ni = 0; ni < 4; ni++) {
                    mma16816(cS[mi][ni], ah[mi], bh[ni]);
                    mma16816(cS[mi][ni], ah[mi], bl[ni]);
                    mma16816(cS[mi][ni], al[mi], bh[ni]);
                }
        }

        // ---- online softmax ----
        float alpha[2][2];
#pragma unroll
        for (int mi = 0; mi < 2; mi++)
#pragma unroll
            for (int j = 0; j < 2; j++) {
                float v = -1e30f;
#pragma unroll
                for (int ni = 0; ni < 4; ni++)
                    v = fmaxf(v, fmaxf(cS[mi][ni][2 * j], cS[mi][ni][2 * j + 1]));
                v = fmaxf(v, __shfl_xor_sync(0xffffffffu, v, 1));
                v = fmaxf(v, __shfl_xor_sync(0xffffffffu, v, 2));
                int row = mw * 32 + mi * 16 + j * 8 + (lane >> 2);
                redm[nh * 64 + row] = v;
            }
        __syncthreads();
#pragma unroll
        for (int mi = 0; mi < 2; mi++)
#pragma unroll
            for (int j = 0; j < 2; j++) {
                int row = mw * 32 + mi * 16 + j * 8 + (lane >> 2);
                float cm = fmaxf(redm[row], redm[64 + row]);
                float mn = fmaxf(m_[mi][j], cm);
                alpha[mi][j] = __expf(m_[mi][j] - mn);
                m_[mi][j] = mn;
            }
        // rescale O
#pragma unroll
        for (int mi = 0; mi < 2; mi++)
#pragma unroll
            for (int nj = 0; nj < 8; nj++) {
                cO[mi][nj][0] *= alpha[mi][0];
                cO[mi][nj][1] *= alpha[mi][0];
                cO[mi][nj][2] *= alpha[mi][1];
                cO[mi][nj][3] *= alpha[mi][1];
            }
        // exp + row sums
#pragma unroll
        for (int mi = 0; mi < 2; mi++)
#pragma unroll
            for (int j = 0; j < 2; j++) {
                float s2 = 0.0f;
#pragma unroll
                for (int ni = 0; ni < 4; ni++) {
                    float e0 = __expf(cS[mi][ni][2 * j] - m_[mi][j]);
                    float e1 = __expf(cS[mi][ni][2 * j + 1] - m_[mi][j]);
                    cS[mi][ni][2 * j] = e0;
                    cS[mi][ni][2 * j + 1] = e1;
                    s2 += e0 + e1;
                }
                s2 += __shfl_xor_sync(0xffffffffu, s2, 1);
                s2 += __shfl_xor_sync(0xffffffffu, s2, 2);
                int row = mw * 32 + mi * 16 + j * 8 + (lane >> 2);
                reds[nh * 64 + row] = s2;
            }
        __syncthreads();
#pragma unroll
        for (int mi = 0; mi < 2; mi++)
#pragma unroll
            for (int j = 0; j < 2; j++) {
                int row = mw * 32 + mi * 16 + j * 8 + (lane >> 2);
                l_[mi][j] = l_[mi][j] * alpha[mi][j] + reds[row] + reds[64 + row];
            }

        // ---- convert P (c-frag -> a-frag identity), hi/lo split ----
        unsigned ph[2][2][4], pl[2][2][4];   // [mi][ks2][reg]
#pragma unroll
        for (int mi = 0; mi < 2; mi++)
#pragma unroll
            for (int ks2 = 0; ks2 < 2; ks2++) {
                split2(cS[mi][2 * ks2][0], cS[mi][2 * ks2][1],
                       ph[mi][ks2][0], pl[mi][ks2][0]);
                split2(cS[mi][2 * ks2][2], cS[mi][2 * ks2][3],
                       ph[mi][ks2][1], pl[mi][ks2][1]);
                split2(cS[mi][2 * ks2 + 1][0], cS[mi][2 * ks2 + 1][1],
                       ph[mi][ks2][2], pl[mi][ks2][2]);
                split2(cS[mi][2 * ks2 + 1][2], cS[mi][2 * ks2 + 1][3],
                       ph[mi][ks2][3], pl[mi][ks2][3]);
            }

        // ---- O += P V over this warp's kv half (k = nh*32 .. +31) ----
#pragma unroll
        for (int ks2 = 0; ks2 < 2; ks2++) {
            unsigned vh[4][4], vl[4][4];     // [npj][reg]
#pragma unroll
            for (int npj = 0; npj < 4; npj++) {
                unsigned voff = (unsigned)((nh * 32 + ks2 * 16 + ((lane >> 3) & 1) * 8 +
                                            (lane & 7)) * 144 +
                                           (npj * 16 + (lane >> 4) * 8) * 2);
                ldsm4t(vh[npj], kb + 18432 + voff);
                ldsm4t(vl[npj], kb + 27648 + voff);
            }
#pragma unroll
            for (int mi = 0; mi < 2; mi++)
#pragma unroll
                for (int nj = 0; nj < 8; nj++) {
                    const unsigned* bbh = &vh[nj >> 1][(nj & 1) * 2];
                    const unsigned* bbl = &vl[nj >> 1][(nj & 1) * 2];
                    mma16816(cO[mi][nj], ph[mi][ks2], bbh);
                    mma16816(cO[mi][nj], ph[mi][ks2], bbl);
                    mma16816(cO[mi][nj], pl[mi][ks2], bbh);
                }
        }
        __syncthreads();   // stage-s readers done before kt+2 overwrites it
    }

    // ---- epilogue: combine the two k-halves, normalize, store ----
    float* osm = (float*)sm;               // 64 x 66 fp32 = 16896 B (< Q area)
    if (nh == 1) {
#pragma unroll
        for (int mi = 0; mi < 2; mi++)
#pragma unroll
            for (int nj = 0; nj < 8; nj++) {
                int r0 = mw * 32 + mi * 16 + (lane >> 2);
                int c0 = nj * 8 + 2 * (lane & 3);
                osm[r0 * 66 + c0]       = cO[mi][nj][0];
                osm[r0 * 66 + c0 + 1]   = cO[mi][nj][1];
                osm[(r0 + 8) * 66 + c0]     = cO[mi][nj][2];
                osm[(r0 + 8) * 66 + c0 + 1] = cO[mi][nj][3];
            }
    }
    __syncthreads();
    if (nh == 0) {
#pragma unroll
        for (int mi = 0; mi < 2; mi++) {
            float i0 = 1.0f / l_[mi][0];
            float i1 = 1.0f / l_[mi][1];
#pragma unroll
            for (int nj = 0; nj < 8; nj++) {
                int r0 = mw * 32 + mi * 16 + (lane >> 2);
                int c0 = nj * 8 + 2 * (lane & 3);
                float2 v0 = make_float2(
                    (cO[mi][nj][0] + osm[r0 * 66 + c0]) * i0,
                    (cO[mi][nj][1] + osm[r0 * 66 + c0 + 1]) * i0);
                float2 v1 = make_float2(
                    (cO[mi][nj][2] + osm[(r0 + 8) * 66 + c0]) * i1,
                    (cO[mi][nj][3] + osm[(r0 + 8) * 66 + c0 + 1]) * i1);
                *(float2*)&out[((size_t)b * NT + q0 + r0) * ND + c0] = v0;
                *(float2*)&out[((size_t)b * NT + q0 + r0 + 8) * ND + c0] = v1;
            }
        }
    }
}

// ===========================================================================
extern "C" void kernel_launch(void* const* d_in, const int* in_sizes, int n_in,
                              void* d_out, int out_size)
{
    (void)in_sizes; (void)n_in; (void)out_size;
    const float* x  = (const float*)d_in[0];
    const float* Wq = (const float*)d_in[1];
    const float* bq = (const float*)d_in[2];
    const float* Wk = (const float*)d_in[3];
    const float* bk = (const float*)d_in[4];
    const float* Wv = (const float*)d_in[5];
    const float* bv = (const float*)d_in[6];
    float* out = (float*)d_out;

    // 0: pre-split W into bf16 hi/lo (192*512 uint pairs)
    wsplit_kernel<<<384, 256>>>(Wq, Wk, Wv);

    // 1: fused QKV projection (tensor cores), writes pre-split q/k/v
    cudaFuncSetAttribute(qkv_kernel,
                         cudaFuncAttributeMaxDynamicSharedMemorySize,
                         QK_TOTAL);
    qkv_kernel<<<(NB * NT) / 128, 256, QK_TOTAL>>>(x, bq, bk, bv);

    // 2: flash attention (tensor cores, 2 CTAs/SM, cp.async double buffer)
    cudaFuncSetAttribute(attn_kernel,
                         cudaFuncAttributeMaxDynamicSharedMemorySize,
                         AT_TOTAL);
    attn_kernel<<<dim3(NT / BQ, NB), 128, AT_TOTAL>>>(out);
}

// round 10
// speedup vs baseline: 3.7059x; 1.0568x over previous
#include <cuda_runtime.h>
#include <cuda_bf16.h>
#include <math.h>

// Problem constants
#define NB 4
#define NT 4096
#define NC 1024
#define ND 64
#define BQ 64           // q rows per CTA (attention)
#define BK 64           // kv tokens per tile (attention)

// Pre-split projections (packed bf16x2 hi/lo, 32 uints per token row).
// Q is stored pre-scaled by 8*log2(e) (score scale folded into exp2 domain).
__device__ unsigned g_qhi[NB * NT * 32];
__device__ unsigned g_qlo[NB * NT * 32];
__device__ unsigned g_khi[NB * NT * 32];
__device__ unsigned g_klo[NB * NT * 32];
__device__ unsigned g_vhi[NB * NT * 32];
__device__ unsigned g_vlo[NB * NT * 32];
// Pre-split W (packed bf16x2 hi/lo): rows 0-63 Wq, 64-127 Wk, 128-191 Wv
__device__ unsigned g_whi[192 * 512];
__device__ unsigned g_wlo[192 * 512];

// ===========================================================================
// Helpers
// ===========================================================================
__device__ __forceinline__ unsigned smem_to_u32(const void* p) {
    unsigned a;
    asm("{ .reg .u64 t; cvta.to.shared.u64 t, %1; cvt.u32.u64 %0, t; }"
        : "=r"(a) : "l"(p));
    return a;
}

__device__ __forceinline__ float ex2(float x) {
    float y;
    asm("ex2.approx.ftz.f32 %0, %1;" : "=f"(y) : "f"(x));
    return y;
}

// bf16 hi/lo split of a float pair, packed little-endian (x in low half)
__device__ __forceinline__ void split2(float x, float y, unsigned& hp, unsigned& lp) {
    __nv_bfloat16 hx = __float2bfloat16(x);
    __nv_bfloat16 hy = __float2bfloat16(y);
    float rx = x - __bfloat162float(hx);
    float ry = y - __bfloat162float(hy);
    __nv_bfloat16 lx = __float2bfloat16(rx);
    __nv_bfloat16 ly = __float2bfloat16(ry);
    hp = ((unsigned)__bfloat16_as_ushort(hy) << 16) | __bfloat16_as_ushort(hx);
    lp = ((unsigned)__bfloat16_as_ushort(ly) << 16) | __bfloat16_as_ushort(lx);
}

// ldmatrix x4, non-transposed
__device__ __forceinline__ void ldsm4(unsigned r[4], unsigned addr) {
    asm volatile("ldmatrix.sync.aligned.m8n8.x4.shared.b16 {%0,%1,%2,%3}, [%4];"
        : "=r"(r[0]), "=r"(r[1]), "=r"(r[2]), "=r"(r[3]) : "r"(addr));
}
// ldmatrix x4, transposed (b16)
__device__ __forceinline__ void ldsm4t(unsigned r[4], unsigned addr) {
    asm volatile("ldmatrix.sync.aligned.m8n8.x4.trans.shared.b16 {%0,%1,%2,%3}, [%4];"
        : "=r"(r[0]), "=r"(r[1]), "=r"(r[2]), "=r"(r[3]) : "r"(addr));
}

// mma.sync m16n8k16 bf16 -> f32 accum
__device__ __forceinline__ void mma16816(float c[4], const unsigned a[4],
                                         const unsigned b[2]) {
    asm volatile(
        "mma.sync.aligned.m16n8k16.row.col.f32.bf16.bf16.f32 "
        "{%0,%1,%2,%3}, {%4,%5,%6,%7}, {%8,%9}, {%0,%1,%2,%3};"
        : "+f"(c[0]), "+f"(c[1]), "+f"(c[2]), "+f"(c[3])
        : "r"(a[0]), "r"(a[1]), "r"(a[2]), "r"(a[3]), "r"(b[0]), "r"(b[1]));
}

// cp.async 16B, L1-bypass
__device__ __forceinline__ void cp16(unsigned dst, const unsigned* src) {
    asm volatile("cp.async.cg.shared.global [%0], [%1], 16;"
        :: "r"(dst), "l"(src));
}
#define CP_COMMIT() asm volatile("cp.async.commit_group;" ::: "memory")
#define CP_WAIT(n)  asm volatile("cp.async.wait_group %0;" :: "n"(n) : "memory")

// ===========================================================================
// Kernel 0: W pre-split (fp32 -> packed bf16 hi/lo), 192 x 1024 elements.
// ===========================================================================
__global__ __launch_bounds__(256) void wsplit_kernel(
    const float* __restrict__ Wq, const float* __restrict__ Wk,
    const float* __restrict__ Wv)
{
    int idx = blockIdx.x * 256 + threadIdx.x;   // 0..98303 (uint pairs)
    int row = idx >> 9;                         // 0..191
    int d2 = idx & 511;
    const float* W = (row < 64) ? Wq : (row < 128 ? Wk : Wv);
    int r = row & 63;
    float2 f = *(const float2*)&W[(size_t)r * NC + d2 * 2];
    unsigned hp, lp;
    split2(f.x, f.y, hp, lp);
    g_whi[idx] = hp;
    g_wlo[idx] = lp;
}

// ===========================================================================
// Kernel 1: fused QKV projection on mma.sync (bf16x3).
// Epilogue writes pre-split packed bf16 hi/lo directly (Q scaled by 8*log2e).
// grid = 128 (M tiles of 128), 256 threads (8 warps = 4 M x 2 N-halves of 96).
// ===========================================================================
#define QK_XHI 0            // 128 x 72 bf16 = 18432 B
#define QK_XLO 18432
#define QK_WHI 36864        // 192 x 72 bf16 = 27648 B
#define QK_WLO 64512
#define QK_TOTAL 92160

__global__ __launch_bounds__(256, 1) void qkv_kernel(
    const float* __restrict__ x,
    const float* __restrict__ bq, const float* __restrict__ bk,
    const float* __restrict__ bv)
{
    extern __shared__ char sm[];
    unsigned smb = smem_to_u32(sm);

    int tid = threadIdx.x;
    int lane = tid & 31;
    int wid = tid >> 5;
    int mw = wid & 3;           // rows mw*32 .. +31
    int nh = wid >> 2;          // cols nh*96 .. +95
    int row0 = blockIdx.x * 128;

    float cO[2][12][4] = {};

    for (int kc = 0; kc < 16; kc++) {
        if (kc) __syncthreads();            // prior chunk's reads done

        // ---- stage X chunk (128 rows x 64 k), split to hi/lo ----
#pragma unroll
        for (int i = 0; i < 16; i++) {
            int idx = tid + i * 256;        // 4096 float2s
            int rr = idx >> 5;
            int d2 = idx & 31;
            float2 f = *(const float2*)&x[(size_t)(row0 + rr) * NC + kc * 64 + d2 * 2];
            unsigned hp, lp;
            split2(f.x, f.y, hp, lp);
            *(unsigned*)(sm + QK_XHI + rr * 144 + d2 * 4) = hp;
            *(unsigned*)(sm + QK_XLO + rr * 144 + d2 * 4) = lp;
        }
        // ---- stage W chunk (192 rows x 64 k), already split ----
#pragma unroll
        for (int i = 0; i < 24; i++) {
            int idx = tid + i * 256;        // 6144 uints
            int rr = idx >> 5;
            int d2 = idx & 31;
            int gsrc = rr * 512 + kc * 32 + d2;
            *(unsigned*)(sm + QK_WHI + rr * 144 + d2 * 4) = g_whi[gsrc];
            *(unsigned*)(sm + QK_WLO + rr * 144 + d2 * 4) = g_wlo[gsrc];
        }
        __syncthreads();

        // ---- MMA: warp tile 32 rows x 96 cols, bf16x3 ----
#pragma unroll
        for (int ks = 0; ks < 4; ks++) {
            unsigned ah[2][4], al[2][4];
#pragma unroll
            for (int mi = 0; mi < 2; mi++) {
                unsigned xoff = (unsigned)((mw * 32 + mi * 16 + (lane & 15)) * 144 +
                                           (ks * 16 + (lane >> 4) * 8) * 2);
                ldsm4(ah[mi], smb + QK_XHI + xoff);
                ldsm4(al[mi], smb + QK_XLO + xoff);
            }
            unsigned bh[12][2], bl[12][2];
#pragma unroll
            for (int np = 0; np < 6; np++) {
                unsigned woff = (unsigned)((nh * 96 + np * 16 + (lane >> 4) * 8 +
                                            (lane & 7)) * 144 +
                                           (ks * 16 + ((lane >> 3) & 1) * 8) * 2);
                unsigned r[4];
                ldsm4(r, smb + QK_WHI + woff);
                bh[2 * np][0] = r[0]; bh[2 * np][1] = r[1];
                bh[2 * np + 1][0] = r[2]; bh[2 * np + 1][1] = r[3];
                ldsm4(r, smb + QK_WLO + woff);
                bl[2 * np][0] = r[0]; bl[2 * np][1] = r[1];
                bl[2 * np + 1][0] = r[2]; bl[2 * np + 1][1] = r[3];
            }
#pragma unroll
            for (int mi = 0; mi < 2; mi++)
#pragma unroll
                for (int nj = 0; nj < 12; nj++) {
                    mma16816(cO[mi][nj], ah[mi], bh[nj]);
                    mma16816(cO[mi][nj], ah[mi], bl[nj]);
                    mma16816(cO[mi][nj], al[mi], bh[nj]);
                }
        }
    }

    // ---- epilogue: add bias, split to bf16 hi/lo, write packed ----
    const float QSCALE = 8.0f * 1.4426950408889634f;   // fold exp2 domain into Q
#pragma unroll
    for (int mi = 0; mi < 2; mi++)
#pragma unroll
        for (int nj = 0; nj < 12; nj++) {
            int gc = nh * 96 + nj * 8 + 2 * (lane & 3);   // global col, even
            unsigned *dhi, *dlo;
            const float* bias;
            int col;
            float scale;
            if (gc < 64)       { dhi = g_qhi; dlo = g_qlo; bias = bq; col = gc; scale = QSCALE; }
            else if (gc < 128) { dhi = g_khi; dlo = g_klo; bias = bk; col = gc - 64; scale = 1.0f; }
            else               { dhi = g_vhi; dlo = g_vlo; bias = bv; col = gc - 128; scale = 1.0f; }
            int r0 = row0 + mw * 32 + mi * 16 + (lane >> 2);
            float b0 = __ldg(&bias[col]);
            float b1 = __ldg(&bias[col + 1]);
            unsigned hp, lp;
            split2((cO[mi][nj][0] + b0) * scale, (cO[mi][nj][1] + b1) * scale, hp, lp);
            dhi[(size_t)r0 * 32 + col / 2] = hp;
            dlo[(size_t)r0 * 32 + col / 2] = lp;
            split2((cO[mi][nj][2] + b0) * scale, (cO[mi][nj][3] + b1) * scale, hp, lp);
            dhi[(size_t)(r0 + 8) * 32 + col / 2] = hp;
            dlo[(size_t)(r0 + 8) * 32 + col / 2] = lp;
        }
}

// ===========================================================================
// Kernel 2: flash attention on mma.sync (HMMA bf16x3).
// grid = (NT/64, NB), 128 threads (4 warps; warp w owns q rows w*16..+15,
// full 64 kv cols -> softmax is warp-local, no cross-warp coupling).
// 2 CTAs/SM; K/V tiles double-buffered via cp.async; Q frags in registers.
// ===========================================================================
#define AT_QHI 0                 // 64 x 144 B = 9216
#define AT_QLO 9216
#define AT_KV  18432             // 2 stages x 36864 (khi,klo,vhi,vlo @ 9216 each)
#define AT_STG 36864
#define AT_TOTAL 92160

__device__ __forceinline__ void stage_kv(unsigned smb, int s, int tid, int kt,
    const unsigned* khi, const unsigned* klo,
    const unsigned* vhi, const unsigned* vlo)
{
    unsigned base = smb + AT_KV + s * AT_STG;
    const unsigned* gs[4] = {khi, klo, vhi, vlo};
#pragma unroll
    for (int a = 0; a < 4; a++)
#pragma unroll
        for (int i = 0; i < 4; i++) {
            int idx = tid + i * 128;      // 0..511
            int rr = idx >> 3;
            int c = idx & 7;
            cp16(base + a * 9216 + rr * 144 + c * 16,
                 gs[a] + (size_t)(kt * BK + rr) * 32 + c * 4);
        }
}

__global__ __launch_bounds__(128, 2) void attn_kernel(float* __restrict__ out)
{
    extern __shared__ char sm[];
    unsigned smb = smem_to_u32(sm);

    int tid = threadIdx.x;
    int lane = tid & 31;
    int w = tid >> 5;            // warp 0..3: q rows w*16 .. +15
    int b = blockIdx.y;
    int q0 = blockIdx.x * BQ;
    int mrow = w * 16;

    const unsigned* qhi = g_qhi + (size_t)b * NT * 32;
    const unsigned* qlo = g_qlo + (size_t)b * NT * 32;
    const unsigned* khi = g_khi + (size_t)b * NT * 32;
    const unsigned* klo = g_klo + (size_t)b * NT * 32;
    const unsigned* vhi = g_vhi + (size_t)b * NT * 32;
    const unsigned* vlo = g_vlo + (size_t)b * NT * 32;

    // ---- stage Q (already split & scaled), then first K/V tile ----
    {
        const unsigned* qs[2] = {qhi, qlo};
#pragma unroll
        for (int a = 0; a < 2; a++)
#pragma unroll
            for (int i = 0; i < 4; i++) {
                int idx = tid + i * 128;
                int rr = idx >> 3;
                int c = idx & 7;
                cp16(smb + a * 9216 + rr * 144 + c * 16,
                     qs[a] + (size_t)(q0 + rr) * 32 + c * 4);
            }
    }
    CP_COMMIT();                                   // G0 = Q
    stage_kv(smb, 0, tid, 0, khi, klo, vhi, vlo);
    CP_COMMIT();                                   // G1 = KV0
    CP_WAIT(1);                                    // Q done
    __syncthreads();

    // ---- hoist Q fragments into registers (once) ----
    unsigned qfh[4][4], qfl[4][4];
#pragma unroll
    for (int ks = 0; ks < 4; ks++) {
        unsigned qoff = (unsigned)((mrow + (lane & 15)) * 144 +
                                   (ks * 16 + (lane >> 4) * 8) * 2);
        ldsm4(qfh[ks], smb + AT_QHI + qoff);
        ldsm4(qfl[ks], smb + AT_QLO + qoff);
    }

    float cO[8][4] = {};
    float m_[2] = {-1e30f, -1e30f};
    float l_[2] = {0.0f, 0.0f};

    for (int kt = 0; kt < NT / BK; kt++) {
        int s = kt & 1;
        unsigned kb = smb + AT_KV + s * AT_STG;          // khi base
        if (kt + 1 < NT / BK) {
            stage_kv(smb, s ^ 1, tid, kt + 1, khi, klo, vhi, vlo);
            CP_COMMIT();
            CP_WAIT(1);
        } else {
            CP_WAIT(0);
        }
        __syncthreads();

        // ---- S = Q K^T, bf16x3: warp tile 16 rows x 64 cols ----
        float cS[8][4] = {};
#pragma unroll
        for (int ks = 0; ks < 4; ks++) {  // d k-chunks of 16
            unsigned bh[8][2], bl[8][2];
#pragma unroll
            for (int np = 0; np < 4; np++) {
                unsigned koff = (unsigned)((np * 16 + (lane >> 4) * 8 +
                                            (lane & 7)) * 144 +
                                           (ks * 16 + ((lane >> 3) & 1) * 8) * 2);
                unsigned r[4];
                ldsm4(r, kb + koff);
                bh[2 * np][0] = r[0]; bh[2 * np][1] = r[1];
                bh[2 * np + 1][0] = r[2]; bh[2 * np + 1][1] = r[3];
                ldsm4(r, kb + 9216 + koff);
                bl[2 * np][0] = r[0]; bl[2 * np][1] = r[1];
                bl[2 * np + 1][0] = r[2]; bl[2 * np + 1][1] = r[3];
            }
#pragma unroll
            for (int nj = 0; nj < 8; nj++) {
                mma16816(cS[nj], qfh[ks], bh[nj]);
                mma16816(cS[nj], qfh[ks], bl[nj]);
                mma16816(cS[nj], qfl[ks], bh[nj]);
            }
        }

        // ---- warp-local online softmax (exp2 domain) ----
        float alpha[2];
#pragma unroll
        for (int j = 0; j < 2; j++) {
            float v = -1e30f;
#pragma unroll
            for (int nj = 0; nj < 8; nj++)
                v = fmaxf(v, fmaxf(cS[nj][2 * j], cS[nj][2 * j + 1]));
            v = fmaxf(v, __shfl_xor_sync(0xffffffffu, v, 1));
            v = fmaxf(v, __shfl_xor_sync(0xffffffffu, v, 2));
            float mn = fmaxf(m_[j], v);
            alpha[j] = ex2(m_[j] - mn);
            m_[j] = mn;
        }
#pragma unroll
        for (int nj = 0; nj < 8; nj++) {
            cO[nj][0] *= alpha[0];
            cO[nj][1] *= alpha[0];
            cO[nj][2] *= alpha[1];
            cO[nj][3] *= alpha[1];
        }
#pragma unroll
        for (int j = 0; j < 2; j++) {
            float s2 = 0.0f;
#pragma unroll
            for (int nj = 0; nj < 8; nj++) {
                float e0 = ex2(cS[nj][2 * j] - m_[j]);
                float e1 = ex2(cS[nj][2 * j + 1] - m_[j]);
                cS[nj][2 * j] = e0;
                cS[nj][2 * j + 1] = e1;
                s2 += e0 + e1;
            }
            s2 += __shfl_xor_sync(0xffffffffu, s2, 1);
            s2 += __shfl_xor_sync(0xffffffffu, s2, 2);
            l_[j] = l_[j] * alpha[j] + s2;
        }

        // ---- convert P (c-frag -> a-frag identity), hi/lo split ----
        unsigned ph[4][4], pl[4][4];      // [ks2][reg], k = 64 kv tokens
#pragma unroll
        for (int ks2 = 0; ks2 < 4; ks2++) {
            split2(cS[2 * ks2][0], cS[2 * ks2][1], ph[ks2][0], pl[ks2][0]);
            split2(cS[2 * ks2][2], cS[2 * ks2][3], ph[ks2][1], pl[ks2][1]);
            split2(cS[2 * ks2 + 1][0], cS[2 * ks2 + 1][1], ph[ks2][2], pl[ks2][2]);
            split2(cS[2 * ks2 + 1][2], cS[2 * ks2 + 1][3], ph[ks2][3], pl[ks2][3]);
        }

        // ---- O += P V (full k = 64) ----
#pragma unroll
        for (int ks2 = 0; ks2 < 4; ks2++) {
            unsigned vh[4][4], vl[4][4];     // [npj][reg]
#pragma unroll
            for (int npj = 0; npj < 4; npj++) {
                unsigned voff = (unsigned)((ks2 * 16 + ((lane >> 3) & 1) * 8 +
                                            (lane & 7)) * 144 +
                                           (npj * 16 + (lane >> 4) * 8) * 2);
                ldsm4t(vh[npj], kb + 18432 + voff);
                ldsm4t(vl[npj], kb + 27648 + voff);
            }
#pragma unroll
            for (int nj = 0; nj < 8; nj++) {
                const unsigned* bbh = &vh[nj >> 1][(nj & 1) * 2];
                const unsigned* bbl = &vl[nj >> 1][(nj & 1) * 2];
                mma16816(cO[nj], ph[ks2], bbh);
                mma16816(cO[nj], ph[ks2], bbl);
                mma16816(cO[nj], pl[ks2], bbh);
            }
        }
        __syncthreads();   // stage-s readers done before kt+2 overwrites it
    }

    // ---- epilogue: normalize, store (warp owns its rows outright) ----
    float i0 = 1.0f / l_[0];
    float i1 = 1.0f / l_[1];
    int r0 = q0 + mrow + (lane >> 2);
#pragma unroll
    for (int nj = 0; nj < 8; nj++) {
        int c0 = nj * 8 + 2 * (lane & 3);
        *(float2*)&out[((size_t)b * NT + r0) * ND + c0] =
            make_float2(cO[nj][0] * i0, cO[nj][1] * i0);
        *(float2*)&out[((size_t)b * NT + r0 + 8) * ND + c0] =
            make_float2(cO[nj][2] * i1, cO[nj][3] * i1);
    }
}

// ===========================================================================
extern "C" void kernel_launch(void* const* d_in, const int* in_sizes, int n_in,
                              void* d_out, int out_size)
{
    (void)in_sizes; (void)n_in; (void)out_size;
    const float* x  = (const float*)d_in[0];
    const float* Wq = (const float*)d_in[1];
    const float* bq = (const float*)d_in[2];
    const float* Wk = (const float*)d_in[3];
    const float* bk = (const float*)d_in[4];
    const float* Wv = (const float*)d_in[5];
    const float* bv = (const float*)d_in[6];
    float* out = (float*)d_out;

    // 0: pre-split W into bf16 hi/lo (192*512 uint pairs)
    wsplit_kernel<<<384, 256>>>(Wq, Wk, Wv);

    // 1: fused QKV projection (tensor cores), writes pre-split q/k/v
    cudaFuncSetAttribute(qkv_kernel,
                         cudaFuncAttributeMaxDynamicSharedMemorySize,
                         QK_TOTAL);
    qkv_kernel<<<(NB * NT) / 128, 256, QK_TOTAL>>>(x, bq, bk, bv);

    // 2: flash attention (tensor cores, 2 CTAs/SM, cp.async double buffer)
    cudaFuncSetAttribute(attn_kernel,
                         cudaFuncAttributeMaxDynamicSharedMemorySize,
                         AT_TOTAL);
    attn_kernel<<<dim3(NT / BQ, NB), 128, AT_TOTAL>>>(out);
}